// round 12
// baseline (speedup 1.0000x reference)
#include <cuda_runtime.h>
#include <cuda_fp16.h>
#include <cstdint>
#include <cstddef>

#define B_SZ 2
#define QL   1024
#define ML   1024
#define KL   2048
#define DM   1024
#define NH   16
#define DH   64

// ============================ helpers =====================================
__device__ __forceinline__ uint32_t smem_u32(const void* p){
    uint32_t a;
    asm("{ .reg .u64 t; cvta.to.shared.u64 t, %1; cvt.u32.u64 %0, t; }" : "=r"(a) : "l"(p));
    return a;
}

#define SWZ(o) ((o) ^ (((o) >> 3) & 0x70))

__device__ __forceinline__ void ldsm_x4(uint32_t& r0, uint32_t& r1, uint32_t& r2,
                                        uint32_t& r3, uint32_t a){
    asm volatile("ldmatrix.sync.aligned.m8n8.x4.shared.b16 {%0,%1,%2,%3},[%4];"
                 : "=r"(r0), "=r"(r1), "=r"(r2), "=r"(r3) : "r"(a));
}
__device__ __forceinline__ void ldsm_x2(uint32_t& r0, uint32_t& r1, uint32_t a){
    asm volatile("ldmatrix.sync.aligned.m8n8.x2.shared.b16 {%0,%1},[%2];"
                 : "=r"(r0), "=r"(r1) : "r"(a));
}
__device__ __forceinline__ void ldsm_x2t(uint32_t& r0, uint32_t& r1, uint32_t a){
    asm volatile("ldmatrix.sync.aligned.m8n8.x2.trans.shared.b16 {%0,%1},[%2];"
                 : "=r"(r0), "=r"(r1) : "r"(a));
}
// fp16 MMA, fp32 accumulate
__device__ __forceinline__ void mma16816(float* c, const uint32_t* a, const uint32_t* b){
    asm volatile(
        "mma.sync.aligned.m16n8k16.row.col.f32.f16.f16.f32 "
        "{%0,%1,%2,%3},{%4,%5,%6,%7},{%8,%9},{%0,%1,%2,%3};"
        : "+f"(c[0]), "+f"(c[1]), "+f"(c[2]), "+f"(c[3])
        : "r"(a[0]), "r"(a[1]), "r"(a[2]), "r"(a[3]), "r"(b[0]), "r"(b[1]));
}

// ============================ scratch pools ===============================
#define SZ_1M ((size_t)1024 * 1024)
#define SZ_2M ((size_t)2048 * 1024)
#define SZ_4M ((size_t)4096 * 1024)
#define SZ_P  ((size_t)B_SZ * NH * QL * KL)

constexpr size_t oHSPh = 0,               oHSPl = oHSPh + SZ_2M;
constexpr size_t oMSPh = oHSPl + SZ_2M,   oMSPl = oMSPh + SZ_2M;
constexpr size_t oRSPh = oMSPl + SZ_2M,   oRSPl = oRSPh + SZ_2M;
constexpr size_t oWT   = oRSPl + SZ_2M;                       // 5 x (hi 1M | lo 1M)
constexpr size_t oQWh  = oWT + 10 * SZ_1M, oQWl = oQWh + SZ_2M;
constexpr size_t oQRh  = oQWl + SZ_2M,    oQRl = oQRh + SZ_2M;
constexpr size_t oKp   = oQRl + SZ_2M;                        // K plain fp16 (4M)
constexpr size_t oRHp  = oKp + SZ_4M;                         // R plain fp16 (2M)
constexpr size_t oVp   = oRHp + SZ_2M;                        // V plain fp16 [tok][feat] (4M)
constexpr size_t oPp   = oVp + SZ_4M;                         // P plain fp16 (64M)
constexpr size_t oSp   = oPp + SZ_P;                          // S  fp16 (64M)
constexpr size_t oBDp  = oSp + SZ_P;                          // BD fp16 (64M)
constexpr size_t oAVp  = oBDp + SZ_P;                         // AV plain fp16 (2M)
constexpr size_t HF_TOTAL = oAVp + SZ_2M;

constexpr size_t fQ  = 0;
constexpr size_t F_TOTAL = fQ + SZ_2M;

__device__ __half g_hf[HF_TOTAL];
__device__ float  g_f [F_TOTAL];

// ============================ GEMM core (3-combo, split x split) ==========
// Used only for the Q projection (accuracy anchor).
template <int NT>
__device__ __forceinline__ void gemm_core(
    const __half* __restrict__ Ahi, const __half* __restrict__ Alo, int lda,
    const __half* __restrict__ Bhi, const __half* __restrict__ Blo, int ldb,
    float* __restrict__ C, int ldc, int K)
{
    __shared__ __align__(1024) uint8_t sA[128 * 128];
    __shared__ __align__(1024) uint8_t sB[NT * 128];

    const int tid  = threadIdx.x;
    const int wid  = tid >> 5;
    const int lane = tid & 31;
    const int wm   = wid & 3;
    const int wn   = wid >> 2;
    constexpr int WN     = NT / 2;
    constexpr int NTILES = WN / 8;
    constexpr int BSEG   = NT / 32;

    const uint32_t a32 = smem_u32(sA), b32 = smem_u32(sB);

    float acc[2][NTILES][4];
#pragma unroll
    for (int mt = 0; mt < 2; mt++)
#pragma unroll
        for (int nt = 0; nt < NTILES; nt++)
#pragma unroll
            for (int q = 0; q < 4; q++) acc[mt][nt][q] = 0.0f;

    uint4 pa[4], pb[BSEG];
    const int nch = K >> 5;

    auto ldg_chunk = [&](int k0){
#pragma unroll
        for (int i = 0; i < 4; i++){
            int s = tid + (i << 8); int row = s >> 3, j = s & 7;
            const __half* p = (j < 4)
                ? Ahi + (size_t)row * lda + k0 + j * 8
                : Alo + (size_t)row * lda + k0 + (j - 4) * 8;
            pa[i] = *reinterpret_cast<const uint4*>(p);
        }
#pragma unroll
        for (int i = 0; i < BSEG; i++){
            int s = tid + (i << 8); int row = s >> 3, j = s & 7;
            const __half* p = (j < 4)
                ? Bhi + (size_t)row * ldb + k0 + j * 8
                : Blo + (size_t)row * ldb + k0 + (j - 4) * 8;
            pb[i] = *reinterpret_cast<const uint4*>(p);
        }
    };

    const uint32_t aRowOff0 = (uint32_t)((wm * 32 + (lane & 15)) << 7) + ((lane >> 4) << 4);
    const uint32_t bRowOff  = (uint32_t)((wn * WN + (lane & 7)) << 7) + (((lane >> 3) & 1) << 4);

    ldg_chunk(0);

    for (int c = 0; c < nch; c++){
#pragma unroll
        for (int i = 0; i < 4; i++){
            int s = tid + (i << 8);
            uint32_t off = (uint32_t)((s >> 3) << 7) + (uint32_t)((s & 7) << 4);
            *reinterpret_cast<uint4*>(sA + SWZ(off)) = pa[i];
        }
#pragma unroll
        for (int i = 0; i < BSEG; i++){
            int s = tid + (i << 8);
            uint32_t off = (uint32_t)((s >> 3) << 7) + (uint32_t)((s & 7) << 4);
            *reinterpret_cast<uint4*>(sB + SWZ(off)) = pb[i];
        }
        __syncthreads();

        if (c + 1 < nch) ldg_chunk((c + 1) << 5);

#pragma unroll
        for (int kh = 0; kh < 2; kh++){
            const uint32_t hiOff = (uint32_t)(kh << 5);
            const uint32_t loOff = hiOff + 64;

            uint32_t ah[2][4], al[2][4];
#pragma unroll
            for (int mt = 0; mt < 2; mt++){
                uint32_t base = aRowOff0 + (uint32_t)(mt << 11);
                ldsm_x4(ah[mt][0], ah[mt][1], ah[mt][2], ah[mt][3],
                        a32 + SWZ(base + hiOff));
                ldsm_x4(al[mt][0], al[mt][1], al[mt][2], al[mt][3],
                        a32 + SWZ(base + loOff));
            }
#pragma unroll
            for (int nt = 0; nt < NTILES; nt++){
                uint32_t b[2];
                ldsm_x2(b[0], b[1], b32 + SWZ(bRowOff + (uint32_t)(nt << 10) + hiOff));
                mma16816(acc[0][nt], ah[0], b);
                mma16816(acc[1][nt], ah[1], b);
                mma16816(acc[0][nt], al[0], b);
                mma16816(acc[1][nt], al[1], b);
            }
#pragma unroll
            for (int nt = 0; nt < NTILES; nt++){
                uint32_t b[2];
                ldsm_x2(b[0], b[1], b32 + SWZ(bRowOff + (uint32_t)(nt << 10) + loOff));
                mma16816(acc[0][nt], ah[0], b);
                mma16816(acc[1][nt], ah[1], b);
            }
        }
        __syncthreads();
    }

    const int r0 = wm * 32 + (lane >> 2);
    const int cc = (lane & 3) * 2;
#pragma unroll
    for (int mt = 0; mt < 2; mt++){
#pragma unroll
        for (int nt = 0; nt < NTILES; nt++){
            const int col = wn * WN + nt * 8 + cc;
            float* p0 = C + (size_t)(r0 + mt * 16) * ldc + col;
            float* p1 = C + (size_t)(r0 + mt * 16 + 8) * ldc + col;
            *reinterpret_cast<float2*>(p0) = make_float2(acc[mt][nt][0], acc[mt][nt][1]);
            *reinterpret_cast<float2*>(p1) = make_float2(acc[mt][nt][2], acc[mt][nt][3]);
        }
    }
}

// ============================ GEMM core (2-combo, split x plain) ==========
template <int NT, bool OUT16>
__device__ __forceinline__ void gemm2_core(
    const __half* __restrict__ Ahi, const __half* __restrict__ Alo, int lda,
    const __half* __restrict__ Bp, int ldb,
    void* __restrict__ Cv, int ldc, int K)
{
    __shared__ __align__(1024) uint8_t sA[16384];
    __shared__ __align__(1024) uint8_t sB[2][NT * 128];

    const int tid  = threadIdx.x;
    const int wid  = tid >> 5;
    const int lane = tid & 31;
    const int wm   = wid & 3;
    const int wn   = wid >> 2;
    constexpr int WN     = NT / 2;
    constexpr int NTILES = WN / 8;
    constexpr int BSEG   = NT / 32;

    const uint32_t a32 = smem_u32(sA), b32 = smem_u32(&sB[0][0]);
    constexpr uint32_t BSTRIDE = (uint32_t)NT * 128;

    float acc[2][NTILES][4];
#pragma unroll
    for (int mt = 0; mt < 2; mt++)
#pragma unroll
        for (int nt = 0; nt < NTILES; nt++)
#pragma unroll
            for (int q = 0; q < 4; q++) acc[mt][nt][q] = 0.0f;

    uint4 pa[4], pb[BSEG];
    const int nch = K >> 5;

    auto ldgA = [&](int k0){
#pragma unroll
        for (int i = 0; i < 4; i++){
            int s = tid + (i << 8); int row = s >> 3, j = s & 7;
            const __half* p = (j < 4)
                ? Ahi + (size_t)row * lda + k0 + j * 8
                : Alo + (size_t)row * lda + k0 + (j - 4) * 8;
            pa[i] = *reinterpret_cast<const uint4*>(p);
        }
    };
    auto ldgB = [&](int k0){
#pragma unroll
        for (int i = 0; i < BSEG; i++){
            int s = tid + (i << 8); int row = s >> 3, j = s & 7;
            pb[i] = *reinterpret_cast<const uint4*>(Bp + (size_t)row * ldb + k0 + j * 8);
        }
    };

    const uint32_t aRowOff0 = (uint32_t)((wm * 32 + (lane & 15)) << 7) + ((lane >> 4) << 4);
    const uint32_t bRowOff  = (uint32_t)((wn * WN + (lane & 7)) << 7) + (((lane >> 3) & 1) << 4);

    ldgA(0);
    ldgB(0);

    for (int c = 0; c < nch; c++){
#pragma unroll
        for (int i = 0; i < 4; i++){
            int s = tid + (i << 8);
            uint32_t off = (uint32_t)((s >> 3) << 7) + (uint32_t)((s & 7) << 4);
            *reinterpret_cast<uint4*>(sA + SWZ(off)) = pa[i];
        }
        if ((c & 1) == 0){
            uint8_t* dst = &sB[(c >> 1) & 1][0];
#pragma unroll
            for (int i = 0; i < BSEG; i++){
                int s = tid + (i << 8);
                uint32_t off = (uint32_t)((s >> 3) << 7) + (uint32_t)((s & 7) << 4);
                *reinterpret_cast<uint4*>(dst + SWZ(off)) = pb[i];
            }
        }
        __syncthreads();

        if (c + 1 < nch) ldgA((c + 1) << 5);
        if ((c & 1) == 1){
            int nk0 = ((c >> 1) + 1) << 6;
            if (nk0 < K) ldgB(nk0);
        }

        const uint32_t bb = b32 + (uint32_t)((c >> 1) & 1) * BSTRIDE;
        const uint32_t bCol = (uint32_t)((c & 1) << 6);

#pragma unroll
        for (int kh = 0; kh < 2; kh++){
            const uint32_t hiOff = (uint32_t)(kh << 5);
            const uint32_t bOff  = bCol + hiOff;

            uint32_t ah[2][4], al[2][4];
#pragma unroll
            for (int mt = 0; mt < 2; mt++){
                uint32_t base = aRowOff0 + (uint32_t)(mt << 11);
                ldsm_x4(ah[mt][0], ah[mt][1], ah[mt][2], ah[mt][3],
                        a32 + SWZ(base + hiOff));
                ldsm_x4(al[mt][0], al[mt][1], al[mt][2], al[mt][3],
                        a32 + SWZ(base + hiOff + 64));
            }
#pragma unroll
            for (int nt = 0; nt < NTILES; nt++){
                uint32_t b[2];
                ldsm_x2(b[0], b[1], bb + SWZ(bRowOff + (uint32_t)(nt << 10) + bOff));
                mma16816(acc[0][nt], ah[0], b);
                mma16816(acc[1][nt], ah[1], b);
                mma16816(acc[0][nt], al[0], b);
                mma16816(acc[1][nt], al[1], b);
            }
        }
        __syncthreads();
    }

    const int r0 = wm * 32 + (lane >> 2);
    const int cc = (lane & 3) * 2;
    if (OUT16){
        __half* Ch = reinterpret_cast<__half*>(Cv);
#pragma unroll
        for (int mt = 0; mt < 2; mt++){
#pragma unroll
            for (int nt = 0; nt < NTILES; nt++){
                const int col = wn * WN + nt * 8 + cc;
                __half2 v0 = __floats2half2_rn(acc[mt][nt][0], acc[mt][nt][1]);
                __half2 v1 = __floats2half2_rn(acc[mt][nt][2], acc[mt][nt][3]);
                *reinterpret_cast<__half2*>(Ch + (size_t)(r0 + mt * 16) * ldc + col)     = v0;
                *reinterpret_cast<__half2*>(Ch + (size_t)(r0 + mt * 16 + 8) * ldc + col) = v1;
            }
        }
    } else {
        float* C = reinterpret_cast<float*>(Cv);
#pragma unroll
        for (int mt = 0; mt < 2; mt++){
#pragma unroll
            for (int nt = 0; nt < NTILES; nt++){
                const int col = wn * WN + nt * 8 + cc;
                float* p0 = C + (size_t)(r0 + mt * 16) * ldc + col;
                float* p1 = C + (size_t)(r0 + mt * 16 + 8) * ldc + col;
                *reinterpret_cast<float2*>(p0) = make_float2(acc[mt][nt][0], acc[mt][nt][1]);
                *reinterpret_cast<float2*>(p1) = make_float2(acc[mt][nt][2], acc[mt][nt][3]);
            }
        }
    }
}

// ============================ GEMM wrappers ===============================
__global__ __launch_bounds__(256)
void k_proj(const __half* __restrict__ Ah, const __half* __restrict__ Al,
            const __half* __restrict__ Bh, const __half* __restrict__ Bl,
            float* __restrict__ C)
{
    size_t ao = (size_t)blockIdx.y * 128 * DM;
    size_t bo = (size_t)blockIdx.x * 128 * DM;
    float* Cp = C + (size_t)blockIdx.y * 128 * DM + blockIdx.x * 128;
    gemm_core<128>(Ah + ao, Al + ao, DM, Bh + bo, Bl + bo, DM, Cp, DM, DM);
}

__global__ __launch_bounds__(256)
void k_proj2_f16(const __half* __restrict__ Ah, const __half* __restrict__ Al,
                 const __half* __restrict__ Bp, __half* __restrict__ C)
{
    size_t ao = (size_t)blockIdx.y * 128 * DM;
    size_t bo = (size_t)blockIdx.x * 128 * DM;
    __half* Cp = C + (size_t)blockIdx.y * 128 * DM + blockIdx.x * 128;
    gemm2_core<128, true>(Ah + ao, Al + ao, DM, Bp + bo, DM, Cp, DM, DM);
}

__global__ __launch_bounds__(256)
void k_projcat2_f16(const __half* __restrict__ Mh, const __half* __restrict__ Ml,
                    const __half* __restrict__ Hh, const __half* __restrict__ Hl,
                    const __half* __restrict__ Bp, __half* __restrict__ C)
{
    const int b = blockIdx.z, m0 = blockIdx.y * 128;
    const __half *Ah, *Al;
    if (m0 < ML){ size_t o = ((size_t)b * ML + m0) * DM; Ah = Mh + o; Al = Ml + o; }
    else        { size_t o = ((size_t)b * QL + (m0 - ML)) * DM; Ah = Hh + o; Al = Hl + o; }
    size_t bo = (size_t)blockIdx.x * 128 * DM;
    __half* Cp = C + ((size_t)b * KL + m0) * DM + blockIdx.x * 128;
    gemm2_core<128, true>(Ah, Al, DM, Bp + bo, DM, Cp, DM, DM);
}

// ============= out projection: A plain x B plain, 1 combo ================
// A: AVp [2048, 1024] fp16. B: WoT [n][k] fp16. C fp32.
__global__ __launch_bounds__(256)
void k_proj1(const __half* __restrict__ Ap, const __half* __restrict__ Bp,
             float* __restrict__ C)
{
    __shared__ __align__(1024) uint8_t sA[16384];
    __shared__ __align__(1024) uint8_t sB[16384];

    const int tid  = threadIdx.x;
    const int wid  = tid >> 5;
    const int lane = tid & 31;
    const int wm   = wid & 3;
    const int wn   = wid >> 2;

    const int m0 = blockIdx.y * 128, n0 = blockIdx.x * 128;
    const uint32_t a32 = smem_u32(sA), b32 = smem_u32(sB);

    float acc[2][8][4];
#pragma unroll
    for (int mt = 0; mt < 2; mt++)
#pragma unroll
        for (int nt = 0; nt < 8; nt++)
#pragma unroll
            for (int q = 0; q < 4; q++) acc[mt][nt][q] = 0.0f;

    uint4 pa[4], pb[4];
    auto ldg_chunk = [&](int k0){
#pragma unroll
        for (int i = 0; i < 4; i++){
            int s = tid + (i << 8); int row = s >> 3, j = s & 7;
            pa[i] = *reinterpret_cast<const uint4*>(Ap + (size_t)(m0 + row) * DM + k0 + j * 8);
        }
#pragma unroll
        for (int i = 0; i < 4; i++){
            int s = tid + (i << 8); int row = s >> 3, j = s & 7;
            pb[i] = *reinterpret_cast<const uint4*>(Bp + (size_t)(n0 + row) * DM + k0 + j * 8);
        }
    };

    const uint32_t aRowOff0 = (uint32_t)((wm * 32 + (lane & 15)) << 7) + ((lane >> 4) << 4);
    const uint32_t bRowOff  = (uint32_t)((wn * 64 + (lane & 7)) << 7) + (((lane >> 3) & 1) << 4);

    ldg_chunk(0);

    for (int c = 0; c < DM / 64; c++){
#pragma unroll
        for (int i = 0; i < 4; i++){
            int s = tid + (i << 8);
            uint32_t off = SWZ((uint32_t)((s >> 3) << 7) + (uint32_t)((s & 7) << 4));
            *reinterpret_cast<uint4*>(sA + off) = pa[i];
        }
#pragma unroll
        for (int i = 0; i < 4; i++){
            int s = tid + (i << 8);
            uint32_t off = SWZ((uint32_t)((s >> 3) << 7) + (uint32_t)((s & 7) << 4));
            *reinterpret_cast<uint4*>(sB + off) = pb[i];
        }
        __syncthreads();

        if (c + 1 < DM / 64) ldg_chunk((c + 1) << 6);

#pragma unroll
        for (int s16 = 0; s16 < 4; s16++){
            const uint32_t kOff = (uint32_t)(s16 << 5);

            uint32_t av[2][4];
#pragma unroll
            for (int mt = 0; mt < 2; mt++){
                uint32_t base = aRowOff0 + (uint32_t)(mt << 11);
                ldsm_x4(av[mt][0], av[mt][1], av[mt][2], av[mt][3],
                        a32 + SWZ(base + kOff));
            }
#pragma unroll
            for (int nt = 0; nt < 8; nt++){
                uint32_t bb[2];
                ldsm_x2(bb[0], bb[1], b32 + SWZ(bRowOff + (uint32_t)(nt << 10) + kOff));
                mma16816(acc[0][nt], av[0], bb);
                mma16816(acc[1][nt], av[1], bb);
            }
        }
        __syncthreads();
    }

    float* Cp = C + (size_t)m0 * DM + n0;
    const int r0 = wm * 32 + (lane >> 2);
    const int cc = (lane & 3) * 2;
#pragma unroll
    for (int mt = 0; mt < 2; mt++){
#pragma unroll
        for (int nt = 0; nt < 8; nt++){
            const int col = wn * 64 + nt * 8 + cc;
            float* p0 = Cp + (size_t)(r0 + mt * 16) * DM + col;
            float* p1 = Cp + (size_t)(r0 + mt * 16 + 8) * DM + col;
            *reinterpret_cast<float2*>(p0) = make_float2(acc[mt][nt][0], acc[mt][nt][1]);
            *reinterpret_cast<float2*>(p1) = make_float2(acc[mt][nt][2], acc[mt][nt][3]);
        }
    }
}

// ============= score kernel: Q split x B plain fp16, K=64, 2-combo =======
// Writes fp16 scores.
__global__ __launch_bounds__(256)
void k_score2(const __half* __restrict__ Qh, const __half* __restrict__ Ql,
              const __half* __restrict__ Bp, __half* __restrict__ Sout, int kBat)
{
    __shared__ __align__(1024) uint8_t sA[32768];
    __shared__ __align__(1024) uint8_t sB[16384];

    const int tid  = threadIdx.x;
    const int wid  = tid >> 5;
    const int lane = tid & 31;
    const int wm   = wid & 3;
    const int wn   = wid >> 2;

    const int z = blockIdx.z, b = z >> 4, h = z & 15;
    const int i0 = blockIdx.y * 128, j0 = blockIdx.x * 128;
    const int hoff = h * DH;

    const uint32_t a32 = smem_u32(sA), b32 = smem_u32(sB);

    {
        const size_t abase = ((size_t)(b * QL + i0)) * DM + hoff;
#pragma unroll
        for (int i = 0; i < 8; i++){
            int s = tid + (i << 8);
            int pg = s >> 10, rem = s & 1023, row = rem >> 3, j = rem & 7;
            const __half* src = (j < 4)
                ? Qh + abase + (size_t)row * DM + pg * 32 + j * 8
                : Ql + abase + (size_t)row * DM + pg * 32 + (j - 4) * 8;
            uint32_t off = (uint32_t)(pg * 16384) + SWZ((uint32_t)(row << 7) + (uint32_t)(j << 4));
            *reinterpret_cast<uint4*>(sA + off) = *reinterpret_cast<const uint4*>(src);
        }
    }
    {
        const size_t bbase = kBat ? ((size_t)(b * KL + j0)) * DM + hoff
                                  : (size_t)j0 * DM + hoff;
#pragma unroll
        for (int i = 0; i < 4; i++){
            int s = tid + (i << 8);
            int row = s >> 3, j = s & 7;
            const __half* src = Bp + bbase + (size_t)row * DM + j * 8;
            uint32_t off = SWZ((uint32_t)(row << 7) + (uint32_t)(j << 4));
            *reinterpret_cast<uint4*>(sB + off) = *reinterpret_cast<const uint4*>(src);
        }
    }
    __syncthreads();

    float acc[2][8][4];
#pragma unroll
    for (int mt = 0; mt < 2; mt++)
#pragma unroll
        for (int nt = 0; nt < 8; nt++)
#pragma unroll
            for (int q = 0; q < 4; q++) acc[mt][nt][q] = 0.0f;

    const uint32_t aRowOff0 = (uint32_t)((wm * 32 + (lane & 15)) << 7) + ((lane >> 4) << 4);
    const uint32_t bRowOff  = (uint32_t)((wn * 64 + (lane & 7)) << 7) + (((lane >> 3) & 1) << 4);

#pragma unroll
    for (int s16 = 0; s16 < 4; s16++){
        const uint32_t apg = (uint32_t)(s16 >> 1) * 16384u;
        const uint32_t hiOff = (uint32_t)((s16 & 1) << 5);
        const uint32_t bOff  = (uint32_t)(s16 << 5);

        uint32_t ah[2][4], al[2][4];
#pragma unroll
        for (int mt = 0; mt < 2; mt++){
            uint32_t base = aRowOff0 + (uint32_t)(mt << 11);
            ldsm_x4(ah[mt][0], ah[mt][1], ah[mt][2], ah[mt][3],
                    a32 + apg + SWZ(base + hiOff));
            ldsm_x4(al[mt][0], al[mt][1], al[mt][2], al[mt][3],
                    a32 + apg + SWZ(base + hiOff + 64));
        }
#pragma unroll
        for (int nt = 0; nt < 8; nt++){
            uint32_t bb[2];
            ldsm_x2(bb[0], bb[1], b32 + SWZ(bRowOff + (uint32_t)(nt << 10) + bOff));
            mma16816(acc[0][nt], ah[0], bb);
            mma16816(acc[1][nt], ah[1], bb);
            mma16816(acc[0][nt], al[0], bb);
            mma16816(acc[1][nt], al[1], bb);
        }
    }

    __half* Cp = Sout + ((size_t)z * QL + i0) * KL + j0;
    const int r0 = wm * 32 + (lane >> 2);
    const int cc = (lane & 3) * 2;
#pragma unroll
    for (int mt = 0; mt < 2; mt++){
#pragma unroll
        for (int nt = 0; nt < 8; nt++){
            const int col = wn * 64 + nt * 8 + cc;
            __half2 v0 = __floats2half2_rn(acc[mt][nt][0], acc[mt][nt][1]);
            __half2 v1 = __floats2half2_rn(acc[mt][nt][2], acc[mt][nt][3]);
            *reinterpret_cast<__half2*>(Cp + (size_t)(r0 + mt * 16) * KL + col)     = v0;
            *reinterpret_cast<__half2*>(Cp + (size_t)(r0 + mt * 16 + 8) * KL + col) = v1;
        }
    }
}

// ===== av kernel: P plain fp16 x V plain fp16 (trans-B), 1 combo =========
// Writes AV as plain fp16.
__global__ __launch_bounds__(256)
void k_av3(const __half* __restrict__ P, const __half* __restrict__ Vp,
           __half* __restrict__ AV)
{
    __shared__ __align__(1024) uint8_t sA[16384];
    __shared__ __align__(1024) uint8_t sB[8192];

    const int tid  = threadIdx.x;
    const int wid  = tid >> 5;
    const int lane = tid & 31;
    const int wm   = wid & 3;
    const int wn   = wid >> 2;

    const int z = blockIdx.z, b = z >> 4, h = z & 15;
    const int i0 = blockIdx.y * 128;
    const size_t prow = (size_t)z * QL + i0;
    const size_t vbase = (size_t)b * KL * DM + h * DH;

    const uint32_t a32 = smem_u32(sA), b32 = smem_u32(sB);

    float acc[2][4][4];
#pragma unroll
    for (int mt = 0; mt < 2; mt++)
#pragma unroll
        for (int nt = 0; nt < 4; nt++)
#pragma unroll
            for (int q = 0; q < 4; q++) acc[mt][nt][q] = 0.0f;

    uint4 pa[4], pb[2];
    auto ldg_chunk = [&](int k0){
#pragma unroll
        for (int i = 0; i < 4; i++){
            int s = tid + (i << 8); int row = s >> 3, j = s & 7;
            pa[i] = *reinterpret_cast<const uint4*>(P + (prow + row) * KL + k0 + j * 8);
        }
#pragma unroll
        for (int i = 0; i < 2; i++){
            int s = tid + (i << 8); int row = s >> 3, j = s & 7;
            pb[i] = *reinterpret_cast<const uint4*>(Vp + vbase + (size_t)(k0 + row) * DM + j * 8);
        }
    };

    const uint32_t aRowOff0 = (uint32_t)((wm * 32 + (lane & 15)) << 7) + ((lane >> 4) << 4);
    const uint32_t n0byte   = (uint32_t)((wn * 32) << 1);

    ldg_chunk(0);

    for (int c = 0; c < KL / 64; c++){
#pragma unroll
        for (int i = 0; i < 4; i++){
            int s = tid + (i << 8);
            uint32_t off = SWZ((uint32_t)((s >> 3) << 7) + (uint32_t)((s & 7) << 4));
            *reinterpret_cast<uint4*>(sA + off) = pa[i];
        }
#pragma unroll
        for (int i = 0; i < 2; i++){
            int s = tid + (i << 8);
            uint32_t off = SWZ((uint32_t)((s >> 3) << 7) + (uint32_t)((s & 7) << 4));
            *reinterpret_cast<uint4*>(sB + off) = pb[i];
        }
        __syncthreads();

        if (c + 1 < KL / 64) ldg_chunk((c + 1) << 6);

#pragma unroll
        for (int s16 = 0; s16 < 4; s16++){
            const uint32_t aOff = (uint32_t)(s16 << 5);

            uint32_t av[2][4];
#pragma unroll
            for (int mt = 0; mt < 2; mt++){
                uint32_t base = aRowOff0 + (uint32_t)(mt << 11);
                ldsm_x4(av[mt][0], av[mt][1], av[mt][2], av[mt][3],
                        a32 + SWZ(base + aOff));
            }
            const uint32_t brow = (uint32_t)(((s16 << 4) + (lane & 15)) << 7);
#pragma unroll
            for (int nt = 0; nt < 4; nt++){
                uint32_t bb[2];
                ldsm_x2t(bb[0], bb[1], b32 + SWZ(brow + n0byte + (uint32_t)(nt << 4)));
                mma16816(acc[0][nt], av[0], bb);
                mma16816(acc[1][nt], av[1], bb);
            }
        }
        __syncthreads();
    }

    __half* Cp = AV + ((size_t)(b * QL + i0)) * DM + h * DH;
    const int r0 = wm * 32 + (lane >> 2);
    const int cc = (lane & 3) * 2;
#pragma unroll
    for (int mt = 0; mt < 2; mt++){
#pragma unroll
        for (int nt = 0; nt < 4; nt++){
            const int col = wn * 32 + nt * 8 + cc;
            __half2 v0 = __floats2half2_rn(acc[mt][nt][0], acc[mt][nt][1]);
            __half2 v1 = __floats2half2_rn(acc[mt][nt][2], acc[mt][nt][3]);
            *reinterpret_cast<__half2*>(Cp + (size_t)(r0 + mt * 16) * DM + col)     = v0;
            *reinterpret_cast<__half2*>(Cp + (size_t)(r0 + mt * 16 + 8) * DM + col) = v1;
        }
    }
}

// ============================ conversions =================================
__device__ __forceinline__ void split1(float x, __half& h, __half& l){
    h = __float2half(x);
    l = __float2half(x - __half2float(h));
}

__global__ __launch_bounds__(256)
void k_split(const float* __restrict__ x, __half* __restrict__ h,
             __half* __restrict__ l, size_t n)
{
    size_t i = ((size_t)blockIdx.x * 256 + threadIdx.x) * 4;
    if (i >= n) return;
    float4 v = *reinterpret_cast<const float4*>(x + i);
    __half h0, h1, h2, h3, l0, l1, l2, l3;
    split1(v.x, h0, l0); split1(v.y, h1, l1);
    split1(v.z, h2, l2); split1(v.w, h3, l3);
    *reinterpret_cast<__half2*>(h + i)     = __halves2half2(h0, h1);
    *reinterpret_cast<__half2*>(h + i + 2) = __halves2half2(h2, h3);
    *reinterpret_cast<__half2*>(l + i)     = __halves2half2(l0, l1);
    *reinterpret_cast<__half2*>(l + i + 2) = __halves2half2(l2, l3);
}

__global__ __launch_bounds__(256)
void k_split_qbias(const float* __restrict__ q,
                   const float* __restrict__ b1, const float* __restrict__ b2,
                   __half* __restrict__ h1, __half* __restrict__ l1,
                   __half* __restrict__ h2, __half* __restrict__ l2,
                   size_t n)
{
    size_t i = ((size_t)blockIdx.x * 256 + threadIdx.x) * 4;
    if (i >= n) return;
    const int col = (int)(i & (DM - 1));
    float4 v = *reinterpret_cast<const float4*>(q + i);
    float4 a = *reinterpret_cast<const float4*>(b1 + col);
    float4 c = *reinterpret_cast<const float4*>(b2 + col);
    __half h0, h1b, h2b, h3, l0, l1b, l2b, l3;
    split1(v.x + a.x, h0, l0);  split1(v.y + a.y, h1b, l1b);
    split1(v.z + a.z, h2b, l2b); split1(v.w + a.w, h3, l3);
    *reinterpret_cast<__half2*>(h1 + i)     = __halves2half2(h0, h1b);
    *reinterpret_cast<__half2*>(h1 + i + 2) = __halves2half2(h2b, h3);
    *reinterpret_cast<__half2*>(l1 + i)     = __halves2half2(l0, l1b);
    *reinterpret_cast<__half2*>(l1 + i + 2) = __halves2half2(l2b, l3);
    split1(v.x + c.x, h0, l0);  split1(v.y + c.y, h1b, l1b);
    split1(v.z + c.z, h2b, l2b); split1(v.w + c.w, h3, l3);
    *reinterpret_cast<__half2*>(h2 + i)     = __halves2half2(h0, h1b);
    *reinterpret_cast<__half2*>(h2 + i + 2) = __halves2half2(h2b, h3);
    *reinterpret_cast<__half2*>(l2 + i)     = __halves2half2(l0, l1b);
    *reinterpret_cast<__half2*>(l2 + i + 2) = __halves2half2(l2b, l3);
}

// out[b][c][r] = split(x[b][r][c]) ; grid (C/32, R/32, batch), block (32,8)
__global__ __launch_bounds__(256)
void k_tsplit(const float* __restrict__ x, __half* __restrict__ th,
              __half* __restrict__ tl, int R, int C)
{
    __shared__ float t[32][33];
    const int bz = blockIdx.z;
    const float* xb = x + (size_t)bz * R * C;
    __half* ph = th + (size_t)bz * R * C;
    __half* pl = tl + (size_t)bz * R * C;
    const int c0 = blockIdx.x * 32, r0 = blockIdx.y * 32;
    const int tx = threadIdx.x, ty = threadIdx.y;
    for (int i = ty; i < 32; i += 8)
        t[i][tx] = xb[(size_t)(r0 + i) * C + c0 + tx];
    __syncthreads();
    for (int i = ty; i < 32; i += 8){
        __half h, l; split1(t[tx][i], h, l);
        ph[(size_t)(c0 + i) * R + r0 + tx] = h;
        pl[(size_t)(c0 + i) * R + r0 + tx] = l;
    }
}

// ============================ softmax (fp16 in) ===========================
__global__ __launch_bounds__(256)
void k_softmax(const __half* __restrict__ S, const __half* __restrict__ BD,
               __half* __restrict__ Pp)
{
    const int row = blockIdx.x;
    const int i   = row & (QL - 1);
    const __half* srow = S + (size_t)row * KL;
    const __half* x0 = BD + (size_t)row * KL;
    const __half* x1 = x0 + KL;

    const int tid = threadIdx.x, lane = tid & 31, warp = tid >> 5;
    __shared__ float red[8];

    float sc[8];
    float mx = -1e30f;
#pragma unroll
    for (int c = 0; c < 8; c++){
        const int j = c * 256 + tid;
        const int d = j - i;
        float bdv;
        if (d <= QL)           bdv = __half2float(x0[j - i + (QL - 1)]);
        else if (d == QL + 1)  bdv = 0.0f;
        else                   bdv = __half2float(x1[j - i - (QL + 2)]);
        const float v = (__half2float(srow[j]) + bdv) * 0.125f;
        sc[c] = v;
        mx = fmaxf(mx, v);
    }
#pragma unroll
    for (int o = 16; o > 0; o >>= 1) mx = fmaxf(mx, __shfl_xor_sync(0xffffffffu, mx, o));
    if (lane == 0) red[warp] = mx;
    __syncthreads();
    float rowmax = red[0];
#pragma unroll
    for (int w = 1; w < 8; w++) rowmax = fmaxf(rowmax, red[w]);
    __syncthreads();

    float sum = 0.0f;
#pragma unroll
    for (int c = 0; c < 8; c++){ sc[c] = __expf(sc[c] - rowmax); sum += sc[c]; }
#pragma unroll
    for (int o = 16; o > 0; o >>= 1) sum += __shfl_xor_sync(0xffffffffu, sum, o);
    if (lane == 0) red[warp] = sum;
    __syncthreads();
    float rowsum = 0.0f;
#pragma unroll
    for (int w = 0; w < 8; w++) rowsum += red[w];
    const float inv = 1.0f / rowsum;

    __half* ph = Pp + (size_t)row * KL;
#pragma unroll
    for (int c = 0; c < 8; c++){
        const int j = c * 256 + tid;
        ph[j] = __float2half(sc[c] * inv);
    }
}

// ============================ launch ======================================
extern "C" void kernel_launch(void* const* d_in, const int* in_sizes, int n_in,
                              void* d_out, int out_size)
{
    const float* h_in  = (const float*)d_in[0];
    const float* mem_p = (const float*)d_in[1];
    const float* r_p   = (const float*)d_in[2];
    const float* W[5]  = { (const float*)d_in[3], (const float*)d_in[4],
                           (const float*)d_in[5], (const float*)d_in[6],
                           (const float*)d_in[7] };   // Wq, Wk, Wv, Wr, Wo
    const float* rwb   = (const float*)d_in[8];
    const float* rrb   = (const float*)d_in[9];
    float* out = (float*)d_out;

    __half* hf; float* fp;
    cudaGetSymbolAddress((void**)&hf, g_hf);
    cudaGetSymbolAddress((void**)&fp, g_f);

    // 1) split inputs (fp16)
    k_split<<<2048, 256>>>(h_in,  hf + oHSPh, hf + oHSPl, SZ_2M);
    k_split<<<2048, 256>>>(mem_p, hf + oMSPh, hf + oMSPl, SZ_2M);
    k_split<<<2048, 256>>>(r_p,   hf + oRSPh, hf + oRSPl, SZ_2M);

    // 2) transpose+split weights: Wt[n][k]
    for (int w = 0; w < 5; w++){
        __half* th = hf + oWT + (size_t)w * 2 * SZ_1M;
        k_tsplit<<<dim3(32, 32, 1), dim3(32, 8)>>>(W[w], th, th + SZ_1M, 1024, 1024);
    }
    const __half *wq = hf + oWT,            *wk = hf + oWT + 2 * SZ_1M,
                 *wv = hf + oWT + 4 * SZ_1M, *wr = hf + oWT + 6 * SZ_1M,
                 *wo = hf + oWT + 8 * SZ_1M;

    // 3) projections
    k_proj<<<dim3(8, 16), 256>>>(hf + oHSPh, hf + oHSPl, wq, wq + SZ_1M, fp + fQ); // Q: 3-combo
    k_projcat2_f16<<<dim3(8, 16, 2), 256>>>(hf + oMSPh, hf + oMSPl,
                                            hf + oHSPh, hf + oHSPl, wk, hf + oKp); // K
    k_projcat2_f16<<<dim3(8, 16, 2), 256>>>(hf + oMSPh, hf + oMSPl,
                                            hf + oHSPh, hf + oHSPl, wv, hf + oVp); // V
    k_proj2_f16<<<dim3(8, 16), 256>>>(hf + oRSPh, hf + oRSPl, wr, hf + oRHp);      // R

    // 4) post-proj conversions (Q only)
    k_split_qbias<<<2048, 256>>>(fp + fQ, rwb, rrb,
                                 hf + oQWh, hf + oQWl, hf + oQRh, hf + oQRl, SZ_2M);

    // 5) scores: 2-combo fp16 -> fp16 out
    k_score2<<<dim3(16, 8, 32), 256>>>(hf + oQWh, hf + oQWl, hf + oKp,  hf + oSp, 1);
    k_score2<<<dim3(16, 8, 32), 256>>>(hf + oQRh, hf + oQRl, hf + oRHp, hf + oBDp, 0);

    // 6) fused rel_shift + softmax (fp16 in) -> plain fp16 probs
    k_softmax<<<B_SZ * NH * QL, 256>>>(hf + oSp, hf + oBDp, hf + oPp);

    // 7) attn_vec = prob @ v (1-combo) -> plain fp16
    k_av3<<<dim3(1, 8, 32), 256>>>(hf + oPp, hf + oVp, hf + oAVp);

    // 8) out = attn_vec @ Wo (1-combo, fp32 out)
    k_proj1<<<dim3(8, 16), 256>>>(hf + oAVp, wo, out);
}

// round 14
// speedup vs baseline: 1.5052x; 1.5052x over previous
#include <cuda_runtime.h>
#include <cuda_fp16.h>
#include <cstdint>
#include <cstddef>

#define B_SZ 2
#define QL   1024
#define ML   1024
#define KL   2048
#define DM   1024
#define NH   16
#define DH   64

// ============================ helpers =====================================
__device__ __forceinline__ uint32_t smem_u32(const void* p){
    uint32_t a;
    asm("{ .reg .u64 t; cvta.to.shared.u64 t, %1; cvt.u32.u64 %0, t; }" : "=r"(a) : "l"(p));
    return a;
}

#define SWZ(o) ((o) ^ (((o) >> 3) & 0x70))

__device__ __forceinline__ void ldsm_x4(uint32_t& r0, uint32_t& r1, uint32_t& r2,
                                        uint32_t& r3, uint32_t a){
    asm volatile("ldmatrix.sync.aligned.m8n8.x4.shared.b16 {%0,%1,%2,%3},[%4];"
                 : "=r"(r0), "=r"(r1), "=r"(r2), "=r"(r3) : "r"(a));
}
__device__ __forceinline__ void ldsm_x2(uint32_t& r0, uint32_t& r1, uint32_t a){
    asm volatile("ldmatrix.sync.aligned.m8n8.x2.shared.b16 {%0,%1},[%2];"
                 : "=r"(r0), "=r"(r1) : "r"(a));
}
__device__ __forceinline__ void ldsm_x2t(uint32_t& r0, uint32_t& r1, uint32_t a){
    asm volatile("ldmatrix.sync.aligned.m8n8.x2.trans.shared.b16 {%0,%1},[%2];"
                 : "=r"(r0), "=r"(r1) : "r"(a));
}
// fp16 MMA, fp32 accumulate
__device__ __forceinline__ void mma16816(float* c, const uint32_t* a, const uint32_t* b){
    asm volatile(
        "mma.sync.aligned.m16n8k16.row.col.f32.f16.f16.f32 "
        "{%0,%1,%2,%3},{%4,%5,%6,%7},{%8,%9},{%0,%1,%2,%3};"
        : "+f"(c[0]), "+f"(c[1]), "+f"(c[2]), "+f"(c[3])
        : "r"(a[0]), "r"(a[1]), "r"(a[2]), "r"(a[3]), "r"(b[0]), "r"(b[1]));
}

// ============================ scratch pools ===============================
#define SZ_1M ((size_t)1024 * 1024)
#define SZ_2M ((size_t)2048 * 1024)
#define SZ_4M ((size_t)4096 * 1024)
#define SZ_P  ((size_t)B_SZ * NH * QL * KL)

constexpr size_t oHSPh = 0,               oHSPl = oHSPh + SZ_2M;
constexpr size_t oMSPh = oHSPl + SZ_2M,   oMSPl = oMSPh + SZ_2M;
constexpr size_t oRSPh = oMSPl + SZ_2M,   oRSPl = oRSPh + SZ_2M;
constexpr size_t oWT   = oRSPl + SZ_2M;                       // 5 x (hi 1M | lo 1M)
constexpr size_t oQWh  = oWT + 10 * SZ_1M, oQWl = oQWh + SZ_2M;
constexpr size_t oQRh  = oQWl + SZ_2M,    oQRl = oQRh + SZ_2M;
constexpr size_t oKp   = oQRl + SZ_2M;                        // K plain fp16 (4M)
constexpr size_t oRHp  = oKp + SZ_4M;                         // R plain fp16 (2M)
constexpr size_t oVp   = oRHp + SZ_2M;                        // V plain fp16 [tok][feat] (4M)
constexpr size_t oPp   = oVp + SZ_4M;                         // P plain fp16 (64M)
constexpr size_t oAVp  = oPp + SZ_P;                          // AV plain fp16 (2M)
constexpr size_t HF_TOTAL = oAVp + SZ_2M;

constexpr size_t fQ  = 0;
constexpr size_t fS  = fQ + SZ_2M;
constexpr size_t fBD = fS + SZ_P;
constexpr size_t F_TOTAL = fBD + SZ_P;

__device__ __half g_hf[HF_TOTAL];
__device__ float  g_f [F_TOTAL];

// ============================ GEMM core (3-combo, split x split) ==========
// Used only for the Q projection (accuracy anchor).
template <int NT>
__device__ __forceinline__ void gemm_core(
    const __half* __restrict__ Ahi, const __half* __restrict__ Alo, int lda,
    const __half* __restrict__ Bhi, const __half* __restrict__ Blo, int ldb,
    float* __restrict__ C, int ldc, int K)
{
    __shared__ __align__(1024) uint8_t sA[128 * 128];
    __shared__ __align__(1024) uint8_t sB[NT * 128];

    const int tid  = threadIdx.x;
    const int wid  = tid >> 5;
    const int lane = tid & 31;
    const int wm   = wid & 3;
    const int wn   = wid >> 2;
    constexpr int WN     = NT / 2;
    constexpr int NTILES = WN / 8;
    constexpr int BSEG   = NT / 32;

    const uint32_t a32 = smem_u32(sA), b32 = smem_u32(sB);

    float acc[2][NTILES][4];
#pragma unroll
    for (int mt = 0; mt < 2; mt++)
#pragma unroll
        for (int nt = 0; nt < NTILES; nt++)
#pragma unroll
            for (int q = 0; q < 4; q++) acc[mt][nt][q] = 0.0f;

    uint4 pa[4], pb[BSEG];
    const int nch = K >> 5;

    auto ldg_chunk = [&](int k0){
#pragma unroll
        for (int i = 0; i < 4; i++){
            int s = tid + (i << 8); int row = s >> 3, j = s & 7;
            const __half* p = (j < 4)
                ? Ahi + (size_t)row * lda + k0 + j * 8
                : Alo + (size_t)row * lda + k0 + (j - 4) * 8;
            pa[i] = *reinterpret_cast<const uint4*>(p);
        }
#pragma unroll
        for (int i = 0; i < BSEG; i++){
            int s = tid + (i << 8); int row = s >> 3, j = s & 7;
            const __half* p = (j < 4)
                ? Bhi + (size_t)row * ldb + k0 + j * 8
                : Blo + (size_t)row * ldb + k0 + (j - 4) * 8;
            pb[i] = *reinterpret_cast<const uint4*>(p);
        }
    };

    const uint32_t aRowOff0 = (uint32_t)((wm * 32 + (lane & 15)) << 7) + ((lane >> 4) << 4);
    const uint32_t bRowOff  = (uint32_t)((wn * WN + (lane & 7)) << 7) + (((lane >> 3) & 1) << 4);

    ldg_chunk(0);

    for (int c = 0; c < nch; c++){
#pragma unroll
        for (int i = 0; i < 4; i++){
            int s = tid + (i << 8);
            uint32_t off = (uint32_t)((s >> 3) << 7) + (uint32_t)((s & 7) << 4);
            *reinterpret_cast<uint4*>(sA + SWZ(off)) = pa[i];
        }
#pragma unroll
        for (int i = 0; i < BSEG; i++){
            int s = tid + (i << 8);
            uint32_t off = (uint32_t)((s >> 3) << 7) + (uint32_t)((s & 7) << 4);
            *reinterpret_cast<uint4*>(sB + SWZ(off)) = pb[i];
        }
        __syncthreads();

        if (c + 1 < nch) ldg_chunk((c + 1) << 5);

#pragma unroll
        for (int kh = 0; kh < 2; kh++){
            const uint32_t hiOff = (uint32_t)(kh << 5);
            const uint32_t loOff = hiOff + 64;

            uint32_t ah[2][4], al[2][4];
#pragma unroll
            for (int mt = 0; mt < 2; mt++){
                uint32_t base = aRowOff0 + (uint32_t)(mt << 11);
                ldsm_x4(ah[mt][0], ah[mt][1], ah[mt][2], ah[mt][3],
                        a32 + SWZ(base + hiOff));
                ldsm_x4(al[mt][0], al[mt][1], al[mt][2], al[mt][3],
                        a32 + SWZ(base + loOff));
            }
#pragma unroll
            for (int nt = 0; nt < NTILES; nt++){
                uint32_t b[2];
                ldsm_x2(b[0], b[1], b32 + SWZ(bRowOff + (uint32_t)(nt << 10) + hiOff));
                mma16816(acc[0][nt], ah[0], b);
                mma16816(acc[1][nt], ah[1], b);
                mma16816(acc[0][nt], al[0], b);
                mma16816(acc[1][nt], al[1], b);
            }
#pragma unroll
            for (int nt = 0; nt < NTILES; nt++){
                uint32_t b[2];
                ldsm_x2(b[0], b[1], b32 + SWZ(bRowOff + (uint32_t)(nt << 10) + loOff));
                mma16816(acc[0][nt], ah[0], b);
                mma16816(acc[1][nt], ah[1], b);
            }
        }
        __syncthreads();
    }

    const int r0 = wm * 32 + (lane >> 2);
    const int cc = (lane & 3) * 2;
#pragma unroll
    for (int mt = 0; mt < 2; mt++){
#pragma unroll
        for (int nt = 0; nt < NTILES; nt++){
            const int col = wn * WN + nt * 8 + cc;
            float* p0 = C + (size_t)(r0 + mt * 16) * ldc + col;
            float* p1 = C + (size_t)(r0 + mt * 16 + 8) * ldc + col;
            *reinterpret_cast<float2*>(p0) = make_float2(acc[mt][nt][0], acc[mt][nt][1]);
            *reinterpret_cast<float2*>(p1) = make_float2(acc[mt][nt][2], acc[mt][nt][3]);
        }
    }
}

// ============================ GEMM core (2-combo, split x plain) ==========
template <int NT, bool OUT16>
__device__ __forceinline__ void gemm2_core(
    const __half* __restrict__ Ahi, const __half* __restrict__ Alo, int lda,
    const __half* __restrict__ Bp, int ldb,
    void* __restrict__ Cv, int ldc, int K)
{
    __shared__ __align__(1024) uint8_t sA[16384];
    __shared__ __align__(1024) uint8_t sB[2][NT * 128];

    const int tid  = threadIdx.x;
    const int wid  = tid >> 5;
    const int lane = tid & 31;
    const int wm   = wid & 3;
    const int wn   = wid >> 2;
    constexpr int WN     = NT / 2;
    constexpr int NTILES = WN / 8;
    constexpr int BSEG   = NT / 32;

    const uint32_t a32 = smem_u32(sA), b32 = smem_u32(&sB[0][0]);
    constexpr uint32_t BSTRIDE = (uint32_t)NT * 128;

    float acc[2][NTILES][4];
#pragma unroll
    for (int mt = 0; mt < 2; mt++)
#pragma unroll
        for (int nt = 0; nt < NTILES; nt++)
#pragma unroll
            for (int q = 0; q < 4; q++) acc[mt][nt][q] = 0.0f;

    uint4 pa[4], pb[BSEG];
    const int nch = K >> 5;

    auto ldgA = [&](int k0){
#pragma unroll
        for (int i = 0; i < 4; i++){
            int s = tid + (i << 8); int row = s >> 3, j = s & 7;
            const __half* p = (j < 4)
                ? Ahi + (size_t)row * lda + k0 + j * 8
                : Alo + (size_t)row * lda + k0 + (j - 4) * 8;
            pa[i] = *reinterpret_cast<const uint4*>(p);
        }
    };
    auto ldgB = [&](int k0){
#pragma unroll
        for (int i = 0; i < BSEG; i++){
            int s = tid + (i << 8); int row = s >> 3, j = s & 7;
            pb[i] = *reinterpret_cast<const uint4*>(Bp + (size_t)row * ldb + k0 + j * 8);
        }
    };

    const uint32_t aRowOff0 = (uint32_t)((wm * 32 + (lane & 15)) << 7) + ((lane >> 4) << 4);
    const uint32_t bRowOff  = (uint32_t)((wn * WN + (lane & 7)) << 7) + (((lane >> 3) & 1) << 4);

    ldgA(0);
    ldgB(0);

    for (int c = 0; c < nch; c++){
#pragma unroll
        for (int i = 0; i < 4; i++){
            int s = tid + (i << 8);
            uint32_t off = (uint32_t)((s >> 3) << 7) + (uint32_t)((s & 7) << 4);
            *reinterpret_cast<uint4*>(sA + SWZ(off)) = pa[i];
        }
        if ((c & 1) == 0){
            uint8_t* dst = &sB[(c >> 1) & 1][0];
#pragma unroll
            for (int i = 0; i < BSEG; i++){
                int s = tid + (i << 8);
                uint32_t off = (uint32_t)((s >> 3) << 7) + (uint32_t)((s & 7) << 4);
                *reinterpret_cast<uint4*>(dst + SWZ(off)) = pb[i];
            }
        }
        __syncthreads();

        if (c + 1 < nch) ldgA((c + 1) << 5);
        if ((c & 1) == 1){
            int nk0 = ((c >> 1) + 1) << 6;
            if (nk0 < K) ldgB(nk0);
        }

        const uint32_t bb = b32 + (uint32_t)((c >> 1) & 1) * BSTRIDE;
        const uint32_t bCol = (uint32_t)((c & 1) << 6);

#pragma unroll
        for (int kh = 0; kh < 2; kh++){
            const uint32_t hiOff = (uint32_t)(kh << 5);
            const uint32_t bOff  = bCol + hiOff;

            uint32_t ah[2][4], al[2][4];
#pragma unroll
            for (int mt = 0; mt < 2; mt++){
                uint32_t base = aRowOff0 + (uint32_t)(mt << 11);
                ldsm_x4(ah[mt][0], ah[mt][1], ah[mt][2], ah[mt][3],
                        a32 + SWZ(base + hiOff));
                ldsm_x4(al[mt][0], al[mt][1], al[mt][2], al[mt][3],
                        a32 + SWZ(base + hiOff + 64));
            }
#pragma unroll
            for (int nt = 0; nt < NTILES; nt++){
                uint32_t b[2];
                ldsm_x2(b[0], b[1], bb + SWZ(bRowOff + (uint32_t)(nt << 10) + bOff));
                mma16816(acc[0][nt], ah[0], b);
                mma16816(acc[1][nt], ah[1], b);
                mma16816(acc[0][nt], al[0], b);
                mma16816(acc[1][nt], al[1], b);
            }
        }
        __syncthreads();
    }

    const int r0 = wm * 32 + (lane >> 2);
    const int cc = (lane & 3) * 2;
    if (OUT16){
        __half* Ch = reinterpret_cast<__half*>(Cv);
#pragma unroll
        for (int mt = 0; mt < 2; mt++){
#pragma unroll
            for (int nt = 0; nt < NTILES; nt++){
                const int col = wn * WN + nt * 8 + cc;
                __half2 v0 = __floats2half2_rn(acc[mt][nt][0], acc[mt][nt][1]);
                __half2 v1 = __floats2half2_rn(acc[mt][nt][2], acc[mt][nt][3]);
                *reinterpret_cast<__half2*>(Ch + (size_t)(r0 + mt * 16) * ldc + col)     = v0;
                *reinterpret_cast<__half2*>(Ch + (size_t)(r0 + mt * 16 + 8) * ldc + col) = v1;
            }
        }
    } else {
        float* C = reinterpret_cast<float*>(Cv);
#pragma unroll
        for (int mt = 0; mt < 2; mt++){
#pragma unroll
            for (int nt = 0; nt < NTILES; nt++){
                const int col = wn * WN + nt * 8 + cc;
                float* p0 = C + (size_t)(r0 + mt * 16) * ldc + col;
                float* p1 = C + (size_t)(r0 + mt * 16 + 8) * ldc + col;
                *reinterpret_cast<float2*>(p0) = make_float2(acc[mt][nt][0], acc[mt][nt][1]);
                *reinterpret_cast<float2*>(p1) = make_float2(acc[mt][nt][2], acc[mt][nt][3]);
            }
        }
    }
}

// ============================ GEMM wrappers ===============================
__global__ __launch_bounds__(256)
void k_proj(const __half* __restrict__ Ah, const __half* __restrict__ Al,
            const __half* __restrict__ Bh, const __half* __restrict__ Bl,
            float* __restrict__ C)
{
    size_t ao = (size_t)blockIdx.y * 128 * DM;
    size_t bo = (size_t)blockIdx.x * 128 * DM;
    float* Cp = C + (size_t)blockIdx.y * 128 * DM + blockIdx.x * 128;
    gemm_core<128>(Ah + ao, Al + ao, DM, Bh + bo, Bl + bo, DM, Cp, DM, DM);
}

__global__ __launch_bounds__(256)
void k_proj2_f16(const __half* __restrict__ Ah, const __half* __restrict__ Al,
                 const __half* __restrict__ Bp, __half* __restrict__ C)
{
    size_t ao = (size_t)blockIdx.y * 128 * DM;
    size_t bo = (size_t)blockIdx.x * 128 * DM;
    __half* Cp = C + (size_t)blockIdx.y * 128 * DM + blockIdx.x * 128;
    gemm2_core<128, true>(Ah + ao, Al + ao, DM, Bp + bo, DM, Cp, DM, DM);
}

__global__ __launch_bounds__(256)
void k_projcat2_f16(const __half* __restrict__ Mh, const __half* __restrict__ Ml,
                    const __half* __restrict__ Hh, const __half* __restrict__ Hl,
                    const __half* __restrict__ Bp, __half* __restrict__ C)
{
    const int b = blockIdx.z, m0 = blockIdx.y * 128;
    const __half *Ah, *Al;
    if (m0 < ML){ size_t o = ((size_t)b * ML + m0) * DM; Ah = Mh + o; Al = Ml + o; }
    else        { size_t o = ((size_t)b * QL + (m0 - ML)) * DM; Ah = Hh + o; Al = Hl + o; }
    size_t bo = (size_t)blockIdx.x * 128 * DM;
    __half* Cp = C + ((size_t)b * KL + m0) * DM + blockIdx.x * 128;
    gemm2_core<128, true>(Ah, Al, DM, Bp + bo, DM, Cp, DM, DM);
}

// ============= out projection: A plain x B plain, 1 combo ================
__global__ __launch_bounds__(256)
void k_proj1(const __half* __restrict__ Ap, const __half* __restrict__ Bp,
             float* __restrict__ C)
{
    __shared__ __align__(1024) uint8_t sA[16384];
    __shared__ __align__(1024) uint8_t sB[16384];

    const int tid  = threadIdx.x;
    const int wid  = tid >> 5;
    const int lane = tid & 31;
    const int wm   = wid & 3;
    const int wn   = wid >> 2;

    const int m0 = blockIdx.y * 128, n0 = blockIdx.x * 128;
    const uint32_t a32 = smem_u32(sA), b32 = smem_u32(sB);

    float acc[2][8][4];
#pragma unroll
    for (int mt = 0; mt < 2; mt++)
#pragma unroll
        for (int nt = 0; nt < 8; nt++)
#pragma unroll
            for (int q = 0; q < 4; q++) acc[mt][nt][q] = 0.0f;

    uint4 pa[4], pb[4];
    auto ldg_chunk = [&](int k0){
#pragma unroll
        for (int i = 0; i < 4; i++){
            int s = tid + (i << 8); int row = s >> 3, j = s & 7;
            pa[i] = *reinterpret_cast<const uint4*>(Ap + (size_t)(m0 + row) * DM + k0 + j * 8);
        }
#pragma unroll
        for (int i = 0; i < 4; i++){
            int s = tid + (i << 8); int row = s >> 3, j = s & 7;
            pb[i] = *reinterpret_cast<const uint4*>(Bp + (size_t)(n0 + row) * DM + k0 + j * 8);
        }
    };

    const uint32_t aRowOff0 = (uint32_t)((wm * 32 + (lane & 15)) << 7) + ((lane >> 4) << 4);
    const uint32_t bRowOff  = (uint32_t)((wn * 64 + (lane & 7)) << 7) + (((lane >> 3) & 1) << 4);

    ldg_chunk(0);

    for (int c = 0; c < DM / 64; c++){
#pragma unroll
        for (int i = 0; i < 4; i++){
            int s = tid + (i << 8);
            uint32_t off = SWZ((uint32_t)((s >> 3) << 7) + (uint32_t)((s & 7) << 4));
            *reinterpret_cast<uint4*>(sA + off) = pa[i];
        }
#pragma unroll
        for (int i = 0; i < 4; i++){
            int s = tid + (i << 8);
            uint32_t off = SWZ((uint32_t)((s >> 3) << 7) + (uint32_t)((s & 7) << 4));
            *reinterpret_cast<uint4*>(sB + off) = pb[i];
        }
        __syncthreads();

        if (c + 1 < DM / 64) ldg_chunk((c + 1) << 6);

#pragma unroll
        for (int s16 = 0; s16 < 4; s16++){
            const uint32_t kOff = (uint32_t)(s16 << 5);

            uint32_t av[2][4];
#pragma unroll
            for (int mt = 0; mt < 2; mt++){
                uint32_t base = aRowOff0 + (uint32_t)(mt << 11);
                ldsm_x4(av[mt][0], av[mt][1], av[mt][2], av[mt][3],
                        a32 + SWZ(base + kOff));
            }
#pragma unroll
            for (int nt = 0; nt < 8; nt++){
                uint32_t bb[2];
                ldsm_x2(bb[0], bb[1], b32 + SWZ(bRowOff + (uint32_t)(nt << 10) + kOff));
                mma16816(acc[0][nt], av[0], bb);
                mma16816(acc[1][nt], av[1], bb);
            }
        }
        __syncthreads();
    }

    float* Cp = C + (size_t)m0 * DM + n0;
    const int r0 = wm * 32 + (lane >> 2);
    const int cc = (lane & 3) * 2;
#pragma unroll
    for (int mt = 0; mt < 2; mt++){
#pragma unroll
        for (int nt = 0; nt < 8; nt++){
            const int col = wn * 64 + nt * 8 + cc;
            float* p0 = Cp + (size_t)(r0 + mt * 16) * DM + col;
            float* p1 = Cp + (size_t)(r0 + mt * 16 + 8) * DM + col;
            *reinterpret_cast<float2*>(p0) = make_float2(acc[mt][nt][0], acc[mt][nt][1]);
            *reinterpret_cast<float2*>(p1) = make_float2(acc[mt][nt][2], acc[mt][nt][3]);
        }
    }
}

// ============= score kernel: Q split x B plain fp16, K=64, 2-combo =======
// fp32 score output (precision-critical).
__global__ __launch_bounds__(256)
void k_score2(const __half* __restrict__ Qh, const __half* __restrict__ Ql,
              const __half* __restrict__ Bp, float* __restrict__ Sout, int kBat)
{
    __shared__ __align__(1024) uint8_t sA[32768];
    __shared__ __align__(1024) uint8_t sB[16384];

    const int tid  = threadIdx.x;
    const int wid  = tid >> 5;
    const int lane = tid & 31;
    const int wm   = wid & 3;
    const int wn   = wid >> 2;

    const int z = blockIdx.z, b = z >> 4, h = z & 15;
    const int i0 = blockIdx.y * 128, j0 = blockIdx.x * 128;
    const int hoff = h * DH;

    const uint32_t a32 = smem_u32(sA), b32 = smem_u32(sB);

    {
        const size_t abase = ((size_t)(b * QL + i0)) * DM + hoff;
#pragma unroll
        for (int i = 0; i < 8; i++){
            int s = tid + (i << 8);
            int pg = s >> 10, rem = s & 1023, row = rem >> 3, j = rem & 7;
            const __half* src = (j < 4)
                ? Qh + abase + (size_t)row * DM + pg * 32 + j * 8
                : Ql + abase + (size_t)row * DM + pg * 32 + (j - 4) * 8;
            uint32_t off = (uint32_t)(pg * 16384) + SWZ((uint32_t)(row << 7) + (uint32_t)(j << 4));
            *reinterpret_cast<uint4*>(sA + off) = *reinterpret_cast<const uint4*>(src);
        }
    }
    {
        const size_t bbase = kBat ? ((size_t)(b * KL + j0)) * DM + hoff
                                  : (size_t)j0 * DM + hoff;
#pragma unroll
        for (int i = 0; i < 4; i++){
            int s = tid + (i << 8);
            int row = s >> 3, j = s & 7;
            const __half* src = Bp + bbase + (size_t)row * DM + j * 8;
            uint32_t off = SWZ((uint32_t)(row << 7) + (uint32_t)(j << 4));
            *reinterpret_cast<uint4*>(sB + off) = *reinterpret_cast<const uint4*>(src);
        }
    }
    __syncthreads();

    float acc[2][8][4];
#pragma unroll
    for (int mt = 0; mt < 2; mt++)
#pragma unroll
        for (int nt = 0; nt < 8; nt++)
#pragma unroll
            for (int q = 0; q < 4; q++) acc[mt][nt][q] = 0.0f;

    const uint32_t aRowOff0 = (uint32_t)((wm * 32 + (lane & 15)) << 7) + ((lane >> 4) << 4);
    const uint32_t bRowOff  = (uint32_t)((wn * 64 + (lane & 7)) << 7) + (((lane >> 3) & 1) << 4);

#pragma unroll
    for (int s16 = 0; s16 < 4; s16++){
        const uint32_t apg = (uint32_t)(s16 >> 1) * 16384u;
        const uint32_t hiOff = (uint32_t)((s16 & 1) << 5);
        const uint32_t bOff  = (uint32_t)(s16 << 5);

        uint32_t ah[2][4], al[2][4];
#pragma unroll
        for (int mt = 0; mt < 2; mt++){
            uint32_t base = aRowOff0 + (uint32_t)(mt << 11);
            ldsm_x4(ah[mt][0], ah[mt][1], ah[mt][2], ah[mt][3],
                    a32 + apg + SWZ(base + hiOff));
            ldsm_x4(al[mt][0], al[mt][1], al[mt][2], al[mt][3],
                    a32 + apg + SWZ(base + hiOff + 64));
        }
#pragma unroll
        for (int nt = 0; nt < 8; nt++){
            uint32_t bb[2];
            ldsm_x2(bb[0], bb[1], b32 + SWZ(bRowOff + (uint32_t)(nt << 10) + bOff));
            mma16816(acc[0][nt], ah[0], bb);
            mma16816(acc[1][nt], ah[1], bb);
            mma16816(acc[0][nt], al[0], bb);
            mma16816(acc[1][nt], al[1], bb);
        }
    }

    float* Cp = Sout + ((size_t)z * QL + i0) * KL + j0;
    const int r0 = wm * 32 + (lane >> 2);
    const int cc = (lane & 3) * 2;
#pragma unroll
    for (int mt = 0; mt < 2; mt++){
#pragma unroll
        for (int nt = 0; nt < 8; nt++){
            const int col = wn * 64 + nt * 8 + cc;
            float* p0 = Cp + (size_t)(r0 + mt * 16) * KL + col;
            float* p1 = Cp + (size_t)(r0 + mt * 16 + 8) * KL + col;
            *reinterpret_cast<float2*>(p0) = make_float2(acc[mt][nt][0], acc[mt][nt][1]);
            *reinterpret_cast<float2*>(p1) = make_float2(acc[mt][nt][2], acc[mt][nt][3]);
        }
    }
}

// ===== av kernel: P plain fp16 x V plain fp16 (trans-B), 1 combo =========
// Writes AV as plain fp16.
__global__ __launch_bounds__(256)
void k_av3(const __half* __restrict__ P, const __half* __restrict__ Vp,
           __half* __restrict__ AV)
{
    __shared__ __align__(1024) uint8_t sA[16384];
    __shared__ __align__(1024) uint8_t sB[8192];

    const int tid  = threadIdx.x;
    const int wid  = tid >> 5;
    const int lane = tid & 31;
    const int wm   = wid & 3;
    const int wn   = wid >> 2;

    const int z = blockIdx.z, b = z >> 4, h = z & 15;
    const int i0 = blockIdx.y * 128;
    const size_t prow = (size_t)z * QL + i0;
    const size_t vbase = (size_t)b * KL * DM + h * DH;

    const uint32_t a32 = smem_u32(sA), b32 = smem_u32(sB);

    float acc[2][4][4];
#pragma unroll
    for (int mt = 0; mt < 2; mt++)
#pragma unroll
        for (int nt = 0; nt < 4; nt++)
#pragma unroll
            for (int q = 0; q < 4; q++) acc[mt][nt][q] = 0.0f;

    uint4 pa[4], pb[2];
    auto ldg_chunk = [&](int k0){
#pragma unroll
        for (int i = 0; i < 4; i++){
            int s = tid + (i << 8); int row = s >> 3, j = s & 7;
            pa[i] = *reinterpret_cast<const uint4*>(P + (prow + row) * KL + k0 + j * 8);
        }
#pragma unroll
        for (int i = 0; i < 2; i++){
            int s = tid + (i << 8); int row = s >> 3, j = s & 7;
            pb[i] = *reinterpret_cast<const uint4*>(Vp + vbase + (size_t)(k0 + row) * DM + j * 8);
        }
    };

    const uint32_t aRowOff0 = (uint32_t)((wm * 32 + (lane & 15)) << 7) + ((lane >> 4) << 4);
    const uint32_t n0byte   = (uint32_t)((wn * 32) << 1);

    ldg_chunk(0);

    for (int c = 0; c < KL / 64; c++){
#pragma unroll
        for (int i = 0; i < 4; i++){
            int s = tid + (i << 8);
            uint32_t off = SWZ((uint32_t)((s >> 3) << 7) + (uint32_t)((s & 7) << 4));
            *reinterpret_cast<uint4*>(sA + off) = pa[i];
        }
#pragma unroll
        for (int i = 0; i < 2; i++){
            int s = tid + (i << 8);
            uint32_t off = SWZ((uint32_t)((s >> 3) << 7) + (uint32_t)((s & 7) << 4));
            *reinterpret_cast<uint4*>(sB + off) = pb[i];
        }
        __syncthreads();

        if (c + 1 < KL / 64) ldg_chunk((c + 1) << 6);

#pragma unroll
        for (int s16 = 0; s16 < 4; s16++){
            const uint32_t aOff = (uint32_t)(s16 << 5);

            uint32_t av[2][4];
#pragma unroll
            for (int mt = 0; mt < 2; mt++){
                uint32_t base = aRowOff0 + (uint32_t)(mt << 11);
                ldsm_x4(av[mt][0], av[mt][1], av[mt][2], av[mt][3],
                        a32 + SWZ(base + aOff));
            }
            const uint32_t brow = (uint32_t)(((s16 << 4) + (lane & 15)) << 7);
#pragma unroll
            for (int nt = 0; nt < 4; nt++){
                uint32_t bb[2];
                ldsm_x2t(bb[0], bb[1], b32 + SWZ(brow + n0byte + (uint32_t)(nt << 4)));
                mma16816(acc[0][nt], av[0], bb);
                mma16816(acc[1][nt], av[1], bb);
            }
        }
        __syncthreads();
    }

    __half* Cp = AV + ((size_t)(b * QL + i0)) * DM + h * DH;
    const int r0 = wm * 32 + (lane >> 2);
    const int cc = (lane & 3) * 2;
#pragma unroll
    for (int mt = 0; mt < 2; mt++){
#pragma unroll
        for (int nt = 0; nt < 4; nt++){
            const int col = wn * 32 + nt * 8 + cc;
            __half2 v0 = __floats2half2_rn(acc[mt][nt][0], acc[mt][nt][1]);
            __half2 v1 = __floats2half2_rn(acc[mt][nt][2], acc[mt][nt][3]);
            *reinterpret_cast<__half2*>(Cp + (size_t)(r0 + mt * 16) * DM + col)     = v0;
            *reinterpret_cast<__half2*>(Cp + (size_t)(r0 + mt * 16 + 8) * DM + col) = v1;
        }
    }
}

// ============================ conversions =================================
__device__ __forceinline__ void split1(float x, __half& h, __half& l){
    h = __float2half(x);
    l = __float2half(x - __half2float(h));
}

__global__ __launch_bounds__(256)
void k_split(const float* __restrict__ x, __half* __restrict__ h,
             __half* __restrict__ l, size_t n)
{
    size_t i = ((size_t)blockIdx.x * 256 + threadIdx.x) * 4;
    if (i >= n) return;
    float4 v = *reinterpret_cast<const float4*>(x + i);
    __half h0, h1, h2, h3, l0, l1, l2, l3;
    split1(v.x, h0, l0); split1(v.y, h1, l1);
    split1(v.z, h2, l2); split1(v.w, h3, l3);
    *reinterpret_cast<__half2*>(h + i)     = __halves2half2(h0, h1);
    *reinterpret_cast<__half2*>(h + i + 2) = __halves2half2(h2, h3);
    *reinterpret_cast<__half2*>(l + i)     = __halves2half2(l0, l1);
    *reinterpret_cast<__half2*>(l + i + 2) = __halves2half2(l2, l3);
}

__global__ __launch_bounds__(256)
void k_split_qbias(const float* __restrict__ q,
                   const float* __restrict__ b1, const float* __restrict__ b2,
                   __half* __restrict__ h1, __half* __restrict__ l1,
                   __half* __restrict__ h2, __half* __restrict__ l2,
                   size_t n)
{
    size_t i = ((size_t)blockIdx.x * 256 + threadIdx.x) * 4;
    if (i >= n) return;
    const int col = (int)(i & (DM - 1));
    float4 v = *reinterpret_cast<const float4*>(q + i);
    float4 a = *reinterpret_cast<const float4*>(b1 + col);
    float4 c = *reinterpret_cast<const float4*>(b2 + col);
    __half h0, h1b, h2b, h3, l0, l1b, l2b, l3;
    split1(v.x + a.x, h0, l0);  split1(v.y + a.y, h1b, l1b);
    split1(v.z + a.z, h2b, l2b); split1(v.w + a.w, h3, l3);
    *reinterpret_cast<__half2*>(h1 + i)     = __halves2half2(h0, h1b);
    *reinterpret_cast<__half2*>(h1 + i + 2) = __halves2half2(h2b, h3);
    *reinterpret_cast<__half2*>(l1 + i)     = __halves2half2(l0, l1b);
    *reinterpret_cast<__half2*>(l1 + i + 2) = __halves2half2(l2b, l3);
    split1(v.x + c.x, h0, l0);  split1(v.y + c.y, h1b, l1b);
    split1(v.z + c.z, h2b, l2b); split1(v.w + c.w, h3, l3);
    *reinterpret_cast<__half2*>(h2 + i)     = __halves2half2(h0, h1b);
    *reinterpret_cast<__half2*>(h2 + i + 2) = __halves2half2(h2b, h3);
    *reinterpret_cast<__half2*>(l2 + i)     = __halves2half2(l0, l1b);
    *reinterpret_cast<__half2*>(l2 + i + 2) = __halves2half2(l2b, l3);
}

// out[b][c][r] = split(x[b][r][c]) ; grid (C/32, R/32, batch), block (32,8)
__global__ __launch_bounds__(256)
void k_tsplit(const float* __restrict__ x, __half* __restrict__ th,
              __half* __restrict__ tl, int R, int C)
{
    __shared__ float t[32][33];
    const int bz = blockIdx.z;
    const float* xb = x + (size_t)bz * R * C;
    __half* ph = th + (size_t)bz * R * C;
    __half* pl = tl + (size_t)bz * R * C;
    const int c0 = blockIdx.x * 32, r0 = blockIdx.y * 32;
    const int tx = threadIdx.x, ty = threadIdx.y;
    for (int i = ty; i < 32; i += 8)
        t[i][tx] = xb[(size_t)(r0 + i) * C + c0 + tx];
    __syncthreads();
    for (int i = ty; i < 32; i += 8){
        __half h, l; split1(t[tx][i], h, l);
        ph[(size_t)(c0 + i) * R + r0 + tx] = h;
        pl[(size_t)(c0 + i) * R + r0 + tx] = l;
    }
}

// ============================ softmax (fp32 in) ===========================
__global__ __launch_bounds__(256)
void k_softmax(const float* __restrict__ S, const float* __restrict__ BD,
               __half* __restrict__ Pp)
{
    const int row = blockIdx.x;
    const int i   = row & (QL - 1);
    const float* srow = S + (size_t)row * KL;
    const float* x0 = BD + (size_t)row * KL;
    const float* x1 = x0 + KL;

    const int tid = threadIdx.x, lane = tid & 31, warp = tid >> 5;
    __shared__ float red[8];

    float sc[8];
    float mx = -1e30f;
#pragma unroll
    for (int c = 0; c < 8; c++){
        const int j = c * 256 + tid;
        const int d = j - i;
        float bdv;
        if (d <= QL)           bdv = x0[j - i + (QL - 1)];
        else if (d == QL + 1)  bdv = 0.0f;
        else                   bdv = x1[j - i - (QL + 2)];
        const float v = (srow[j] + bdv) * 0.125f;
        sc[c] = v;
        mx = fmaxf(mx, v);
    }
#pragma unroll
    for (int o = 16; o > 0; o >>= 1) mx = fmaxf(mx, __shfl_xor_sync(0xffffffffu, mx, o));
    if (lane == 0) red[warp] = mx;
    __syncthreads();
    float rowmax = red[0];
#pragma unroll
    for (int w = 1; w < 8; w++) rowmax = fmaxf(rowmax, red[w]);
    __syncthreads();

    float sum = 0.0f;
#pragma unroll
    for (int c = 0; c < 8; c++){ sc[c] = __expf(sc[c] - rowmax); sum += sc[c]; }
#pragma unroll
    for (int o = 16; o > 0; o >>= 1) sum += __shfl_xor_sync(0xffffffffu, sum, o);
    if (lane == 0) red[warp] = sum;
    __syncthreads();
    float rowsum = 0.0f;
#pragma unroll
    for (int w = 0; w < 8; w++) rowsum += red[w];
    const float inv = 1.0f / rowsum;

    __half* ph = Pp + (size_t)row * KL;
#pragma unroll
    for (int c = 0; c < 8; c++){
        const int j = c * 256 + tid;
        ph[j] = __float2half(sc[c] * inv);
    }
}

// ============================ launch ======================================
extern "C" void kernel_launch(void* const* d_in, const int* in_sizes, int n_in,
                              void* d_out, int out_size)
{
    const float* h_in  = (const float*)d_in[0];
    const float* mem_p = (const float*)d_in[1];
    const float* r_p   = (const float*)d_in[2];
    const float* W[5]  = { (const float*)d_in[3], (const float*)d_in[4],
                           (const float*)d_in[5], (const float*)d_in[6],
                           (const float*)d_in[7] };   // Wq, Wk, Wv, Wr, Wo
    const float* rwb   = (const float*)d_in[8];
    const float* rrb   = (const float*)d_in[9];
    float* out = (float*)d_out;

    __half* hf; float* fp;
    cudaGetSymbolAddress((void**)&hf, g_hf);
    cudaGetSymbolAddress((void**)&fp, g_f);

    // 1) split inputs (fp16)
    k_split<<<2048, 256>>>(h_in,  hf + oHSPh, hf + oHSPl, SZ_2M);
    k_split<<<2048, 256>>>(mem_p, hf + oMSPh, hf + oMSPl, SZ_2M);
    k_split<<<2048, 256>>>(r_p,   hf + oRSPh, hf + oRSPl, SZ_2M);

    // 2) transpose+split weights: Wt[n][k]
    for (int w = 0; w < 5; w++){
        __half* th = hf + oWT + (size_t)w * 2 * SZ_1M;
        k_tsplit<<<dim3(32, 32, 1), dim3(32, 8)>>>(W[w], th, th + SZ_1M, 1024, 1024);
    }
    const __half *wq = hf + oWT,            *wk = hf + oWT + 2 * SZ_1M,
                 *wv = hf + oWT + 4 * SZ_1M, *wr = hf + oWT + 6 * SZ_1M,
                 *wo = hf + oWT + 8 * SZ_1M;

    // 3) projections
    k_proj<<<dim3(8, 16), 256>>>(hf + oHSPh, hf + oHSPl, wq, wq + SZ_1M, fp + fQ); // Q: 3-combo
    k_projcat2_f16<<<dim3(8, 16, 2), 256>>>(hf + oMSPh, hf + oMSPl,
                                            hf + oHSPh, hf + oHSPl, wk, hf + oKp); // K
    k_projcat2_f16<<<dim3(8, 16, 2), 256>>>(hf + oMSPh, hf + oMSPl,
                                            hf + oHSPh, hf + oHSPl, wv, hf + oVp); // V
    k_proj2_f16<<<dim3(8, 16), 256>>>(hf + oRSPh, hf + oRSPl, wr, hf + oRHp);      // R

    // 4) post-proj conversions (Q only)
    k_split_qbias<<<2048, 256>>>(fp + fQ, rwb, rrb,
                                 hf + oQWh, hf + oQWl, hf + oQRh, hf + oQRl, SZ_2M);

    // 5) scores: 2-combo fp16 -> fp32 out
    k_score2<<<dim3(16, 8, 32), 256>>>(hf + oQWh, hf + oQWl, hf + oKp,  fp + fS, 1);
    k_score2<<<dim3(16, 8, 32), 256>>>(hf + oQRh, hf + oQRl, hf + oRHp, fp + fBD, 0);

    // 6) fused rel_shift + softmax -> plain fp16 probs
    k_softmax<<<B_SZ * NH * QL, 256>>>(fp + fS, fp + fBD, hf + oPp);

    // 7) attn_vec = prob @ v (1-combo) -> plain fp16
    k_av3<<<dim3(1, 8, 32), 256>>>(hf + oPp, hf + oVp, hf + oAVp);

    // 8) out = attn_vec @ Wo (1-combo, fp32 out)
    k_proj1<<<dim3(8, 16), 256>>>(hf + oAVp, wo, out);
}

// round 15
// speedup vs baseline: 1.5374x; 1.0214x over previous
#include <cuda_runtime.h>
#include <cuda_fp16.h>
#include <cstdint>
#include <cstddef>

#define B_SZ 2
#define QL   1024
#define ML   1024
#define KL   2048
#define DM   1024
#define NH   16
#define DH   64

// ============================ helpers =====================================
__device__ __forceinline__ uint32_t smem_u32(const void* p){
    uint32_t a;
    asm("{ .reg .u64 t; cvta.to.shared.u64 t, %1; cvt.u32.u64 %0, t; }" : "=r"(a) : "l"(p));
    return a;
}

#define SWZ(o) ((o) ^ (((o) >> 3) & 0x70))

__device__ __forceinline__ void ldsm_x4(uint32_t& r0, uint32_t& r1, uint32_t& r2,
                                        uint32_t& r3, uint32_t a){
    asm volatile("ldmatrix.sync.aligned.m8n8.x4.shared.b16 {%0,%1,%2,%3},[%4];"
                 : "=r"(r0), "=r"(r1), "=r"(r2), "=r"(r3) : "r"(a));
}
__device__ __forceinline__ void ldsm_x2(uint32_t& r0, uint32_t& r1, uint32_t a){
    asm volatile("ldmatrix.sync.aligned.m8n8.x2.shared.b16 {%0,%1},[%2];"
                 : "=r"(r0), "=r"(r1) : "r"(a));
}
__device__ __forceinline__ void ldsm_x2t(uint32_t& r0, uint32_t& r1, uint32_t a){
    asm volatile("ldmatrix.sync.aligned.m8n8.x2.trans.shared.b16 {%0,%1},[%2];"
                 : "=r"(r0), "=r"(r1) : "r"(a));
}
// fp16 MMA, fp32 accumulate
__device__ __forceinline__ void mma16816(float* c, const uint32_t* a, const uint32_t* b){
    asm volatile(
        "mma.sync.aligned.m16n8k16.row.col.f32.f16.f16.f32 "
        "{%0,%1,%2,%3},{%4,%5,%6,%7},{%8,%9},{%0,%1,%2,%3};"
        : "+f"(c[0]), "+f"(c[1]), "+f"(c[2]), "+f"(c[3])
        : "r"(a[0]), "r"(a[1]), "r"(a[2]), "r"(a[3]), "r"(b[0]), "r"(b[1]));
}

// ============================ scratch pools ===============================
#define SZ_1M ((size_t)1024 * 1024)
#define SZ_2M ((size_t)2048 * 1024)
#define SZ_4M ((size_t)4096 * 1024)
#define SZ_P  ((size_t)B_SZ * NH * QL * KL)

constexpr size_t oHSPh = 0,               oHSPl = oHSPh + SZ_2M;
constexpr size_t oMSPh = oHSPl + SZ_2M,   oMSPl = oMSPh + SZ_2M;
constexpr size_t oRSPh = oMSPl + SZ_2M,   oRSPl = oRSPh + SZ_2M;
constexpr size_t oWT   = oRSPl + SZ_2M;                       // 5 x (hi 1M | lo 1M)
constexpr size_t oQWh  = oWT + 10 * SZ_1M, oQWl = oQWh + SZ_2M;
constexpr size_t oQRh  = oQWl + SZ_2M,    oQRl = oQRh + SZ_2M;
constexpr size_t oKp   = oQRl + SZ_2M;                        // K plain fp16 (4M)
constexpr size_t oRHp  = oKp + SZ_4M;                         // R plain fp16 (2M)
constexpr size_t oVp   = oRHp + SZ_2M;                        // V plain fp16 [tok][feat] (4M)
constexpr size_t oPp   = oVp + SZ_4M;                         // P plain fp16 (64M)
constexpr size_t oAVp  = oPp + SZ_P;                          // AV plain fp16 (2M)
constexpr size_t HF_TOTAL = oAVp + SZ_2M;

constexpr size_t fS  = 0;
constexpr size_t fBD = fS + SZ_P;
constexpr size_t F_TOTAL = fBD + SZ_P;

__device__ __half g_hf[HF_TOTAL];
__device__ float  g_f [F_TOTAL];

// ====== Q projection: 3-combo split x split + fused bias-add + split ======
// C = (HSPh+HSPl) @ (Wqh+Wql)^T (dropping lo*lo); epilogue adds rwb / rrb
// per column in fp32 and writes QW (hi/lo) and QR (hi/lo) fp16 directly.
__global__ __launch_bounds__(256)
void k_projq(const __half* __restrict__ Ahi, const __half* __restrict__ Alo,
             const __half* __restrict__ Bhi, const __half* __restrict__ Blo,
             const float* __restrict__ b1, const float* __restrict__ b2,
             __half* __restrict__ QWh, __half* __restrict__ QWl,
             __half* __restrict__ QRh, __half* __restrict__ QRl)
{
    __shared__ __align__(1024) uint8_t sA[128 * 128];
    __shared__ __align__(1024) uint8_t sB[128 * 128];

    const int tid  = threadIdx.x;
    const int wid  = tid >> 5;
    const int lane = tid & 31;
    const int wm   = wid & 3;
    const int wn   = wid >> 2;

    const size_t ao = (size_t)blockIdx.y * 128 * DM;
    const size_t bo = (size_t)blockIdx.x * 128 * DM;
    const int n0 = blockIdx.x * 128, m0 = blockIdx.y * 128;

    const uint32_t a32 = smem_u32(sA), b32 = smem_u32(sB);

    float acc[2][8][4];
#pragma unroll
    for (int mt = 0; mt < 2; mt++)
#pragma unroll
        for (int nt = 0; nt < 8; nt++)
#pragma unroll
            for (int q = 0; q < 4; q++) acc[mt][nt][q] = 0.0f;

    uint4 pa[4], pb[4];
    auto ldg_chunk = [&](int k0){
#pragma unroll
        for (int i = 0; i < 4; i++){
            int s = tid + (i << 8); int row = s >> 3, j = s & 7;
            const __half* p = (j < 4)
                ? Ahi + ao + (size_t)row * DM + k0 + j * 8
                : Alo + ao + (size_t)row * DM + k0 + (j - 4) * 8;
            pa[i] = *reinterpret_cast<const uint4*>(p);
        }
#pragma unroll
        for (int i = 0; i < 4; i++){
            int s = tid + (i << 8); int row = s >> 3, j = s & 7;
            const __half* p = (j < 4)
                ? Bhi + bo + (size_t)row * DM + k0 + j * 8
                : Blo + bo + (size_t)row * DM + k0 + (j - 4) * 8;
            pb[i] = *reinterpret_cast<const uint4*>(p);
        }
    };

    const uint32_t aRowOff0 = (uint32_t)((wm * 32 + (lane & 15)) << 7) + ((lane >> 4) << 4);
    const uint32_t bRowOff  = (uint32_t)((wn * 64 + (lane & 7)) << 7) + (((lane >> 3) & 1) << 4);

    ldg_chunk(0);

    for (int c = 0; c < DM / 32; c++){
#pragma unroll
        for (int i = 0; i < 4; i++){
            int s = tid + (i << 8);
            uint32_t off = (uint32_t)((s >> 3) << 7) + (uint32_t)((s & 7) << 4);
            *reinterpret_cast<uint4*>(sA + SWZ(off)) = pa[i];
        }
#pragma unroll
        for (int i = 0; i < 4; i++){
            int s = tid + (i << 8);
            uint32_t off = (uint32_t)((s >> 3) << 7) + (uint32_t)((s & 7) << 4);
            *reinterpret_cast<uint4*>(sB + SWZ(off)) = pb[i];
        }
        __syncthreads();

        if (c + 1 < DM / 32) ldg_chunk((c + 1) << 5);

#pragma unroll
        for (int kh = 0; kh < 2; kh++){
            const uint32_t hiOff = (uint32_t)(kh << 5);
            const uint32_t loOff = hiOff + 64;

            uint32_t ah[2][4], al[2][4];
#pragma unroll
            for (int mt = 0; mt < 2; mt++){
                uint32_t base = aRowOff0 + (uint32_t)(mt << 11);
                ldsm_x4(ah[mt][0], ah[mt][1], ah[mt][2], ah[mt][3],
                        a32 + SWZ(base + hiOff));
                ldsm_x4(al[mt][0], al[mt][1], al[mt][2], al[mt][3],
                        a32 + SWZ(base + loOff));
            }
#pragma unroll
            for (int nt = 0; nt < 8; nt++){
                uint32_t b[2];
                ldsm_x2(b[0], b[1], b32 + SWZ(bRowOff + (uint32_t)(nt << 10) + hiOff));
                mma16816(acc[0][nt], ah[0], b);
                mma16816(acc[1][nt], ah[1], b);
                mma16816(acc[0][nt], al[0], b);
                mma16816(acc[1][nt], al[1], b);
            }
#pragma unroll
            for (int nt = 0; nt < 8; nt++){
                uint32_t b[2];
                ldsm_x2(b[0], b[1], b32 + SWZ(bRowOff + (uint32_t)(nt << 10) + loOff));
                mma16816(acc[0][nt], ah[0], b);
                mma16816(acc[1][nt], ah[1], b);
            }
        }
        __syncthreads();
    }

    // epilogue: add bias (fp32), split to fp16 hi/lo, write QW and QR
    const int r0 = wm * 32 + (lane >> 2);
    const int cc = (lane & 3) * 2;
#pragma unroll
    for (int mt = 0; mt < 2; mt++){
#pragma unroll
        for (int nt = 0; nt < 8; nt++){
            const int col = n0 + wn * 64 + nt * 8 + cc;
            float2 bw = *reinterpret_cast<const float2*>(b1 + col);
            float2 br = *reinterpret_cast<const float2*>(b2 + col);
#pragma unroll
            for (int half = 0; half < 2; half++){
                const size_t row = (size_t)(m0 + r0 + mt * 16 + half * 8);
                const float v0 = acc[mt][nt][half * 2 + 0];
                const float v1 = acc[mt][nt][half * 2 + 1];
                // QW = v + rwb
                float w0 = v0 + bw.x, w1 = v1 + bw.y;
                __half w0h = __float2half(w0), w1h = __float2half(w1);
                __half w0l = __float2half(w0 - __half2float(w0h));
                __half w1l = __float2half(w1 - __half2float(w1h));
                *reinterpret_cast<__half2*>(QWh + row * DM + col) = __halves2half2(w0h, w1h);
                *reinterpret_cast<__half2*>(QWl + row * DM + col) = __halves2half2(w0l, w1l);
                // QR = v + rrb
                float r0f = v0 + br.x, r1f = v1 + br.y;
                __half r0h = __float2half(r0f), r1h = __float2half(r1f);
                __half r0l = __float2half(r0f - __half2float(r0h));
                __half r1l = __float2half(r1f - __half2float(r1h));
                *reinterpret_cast<__half2*>(QRh + row * DM + col) = __halves2half2(r0h, r1h);
                *reinterpret_cast<__half2*>(QRl + row * DM + col) = __halves2half2(r0l, r1l);
            }
        }
    }
}

// ============================ GEMM core (2-combo, split x plain) ==========
template <int NT, bool OUT16>
__device__ __forceinline__ void gemm2_core(
    const __half* __restrict__ Ahi, const __half* __restrict__ Alo, int lda,
    const __half* __restrict__ Bp, int ldb,
    void* __restrict__ Cv, int ldc, int K)
{
    __shared__ __align__(1024) uint8_t sA[16384];
    __shared__ __align__(1024) uint8_t sB[2][NT * 128];

    const int tid  = threadIdx.x;
    const int wid  = tid >> 5;
    const int lane = tid & 31;
    const int wm   = wid & 3;
    const int wn   = wid >> 2;
    constexpr int WN     = NT / 2;
    constexpr int NTILES = WN / 8;
    constexpr int BSEG   = NT / 32;

    const uint32_t a32 = smem_u32(sA), b32 = smem_u32(&sB[0][0]);
    constexpr uint32_t BSTRIDE = (uint32_t)NT * 128;

    float acc[2][NTILES][4];
#pragma unroll
    for (int mt = 0; mt < 2; mt++)
#pragma unroll
        for (int nt = 0; nt < NTILES; nt++)
#pragma unroll
            for (int q = 0; q < 4; q++) acc[mt][nt][q] = 0.0f;

    uint4 pa[4], pb[BSEG];
    const int nch = K >> 5;

    auto ldgA = [&](int k0){
#pragma unroll
        for (int i = 0; i < 4; i++){
            int s = tid + (i << 8); int row = s >> 3, j = s & 7;
            const __half* p = (j < 4)
                ? Ahi + (size_t)row * lda + k0 + j * 8
                : Alo + (size_t)row * lda + k0 + (j - 4) * 8;
            pa[i] = *reinterpret_cast<const uint4*>(p);
        }
    };
    auto ldgB = [&](int k0){
#pragma unroll
        for (int i = 0; i < BSEG; i++){
            int s = tid + (i << 8); int row = s >> 3, j = s & 7;
            pb[i] = *reinterpret_cast<const uint4*>(Bp + (size_t)row * ldb + k0 + j * 8);
        }
    };

    const uint32_t aRowOff0 = (uint32_t)((wm * 32 + (lane & 15)) << 7) + ((lane >> 4) << 4);
    const uint32_t bRowOff  = (uint32_t)((wn * WN + (lane & 7)) << 7) + (((lane >> 3) & 1) << 4);

    ldgA(0);
    ldgB(0);

    for (int c = 0; c < nch; c++){
#pragma unroll
        for (int i = 0; i < 4; i++){
            int s = tid + (i << 8);
            uint32_t off = (uint32_t)((s >> 3) << 7) + (uint32_t)((s & 7) << 4);
            *reinterpret_cast<uint4*>(sA + SWZ(off)) = pa[i];
        }
        if ((c & 1) == 0){
            uint8_t* dst = &sB[(c >> 1) & 1][0];
#pragma unroll
            for (int i = 0; i < BSEG; i++){
                int s = tid + (i << 8);
                uint32_t off = (uint32_t)((s >> 3) << 7) + (uint32_t)((s & 7) << 4);
                *reinterpret_cast<uint4*>(dst + SWZ(off)) = pb[i];
            }
        }
        __syncthreads();

        if (c + 1 < nch) ldgA((c + 1) << 5);
        if ((c & 1) == 1){
            int nk0 = ((c >> 1) + 1) << 6;
            if (nk0 < K) ldgB(nk0);
        }

        const uint32_t bb = b32 + (uint32_t)((c >> 1) & 1) * BSTRIDE;
        const uint32_t bCol = (uint32_t)((c & 1) << 6);

#pragma unroll
        for (int kh = 0; kh < 2; kh++){
            const uint32_t hiOff = (uint32_t)(kh << 5);
            const uint32_t bOff  = bCol + hiOff;

            uint32_t ah[2][4], al[2][4];
#pragma unroll
            for (int mt = 0; mt < 2; mt++){
                uint32_t base = aRowOff0 + (uint32_t)(mt << 11);
                ldsm_x4(ah[mt][0], ah[mt][1], ah[mt][2], ah[mt][3],
                        a32 + SWZ(base + hiOff));
                ldsm_x4(al[mt][0], al[mt][1], al[mt][2], al[mt][3],
                        a32 + SWZ(base + hiOff + 64));
            }
#pragma unroll
            for (int nt = 0; nt < NTILES; nt++){
                uint32_t b[2];
                ldsm_x2(b[0], b[1], bb + SWZ(bRowOff + (uint32_t)(nt << 10) + bOff));
                mma16816(acc[0][nt], ah[0], b);
                mma16816(acc[1][nt], ah[1], b);
                mma16816(acc[0][nt], al[0], b);
                mma16816(acc[1][nt], al[1], b);
            }
        }
        __syncthreads();
    }

    const int r0 = wm * 32 + (lane >> 2);
    const int cc = (lane & 3) * 2;
    if (OUT16){
        __half* Ch = reinterpret_cast<__half*>(Cv);
#pragma unroll
        for (int mt = 0; mt < 2; mt++){
#pragma unroll
            for (int nt = 0; nt < NTILES; nt++){
                const int col = wn * WN + nt * 8 + cc;
                __half2 v0 = __floats2half2_rn(acc[mt][nt][0], acc[mt][nt][1]);
                __half2 v1 = __floats2half2_rn(acc[mt][nt][2], acc[mt][nt][3]);
                *reinterpret_cast<__half2*>(Ch + (size_t)(r0 + mt * 16) * ldc + col)     = v0;
                *reinterpret_cast<__half2*>(Ch + (size_t)(r0 + mt * 16 + 8) * ldc + col) = v1;
            }
        }
    } else {
        float* C = reinterpret_cast<float*>(Cv);
#pragma unroll
        for (int mt = 0; mt < 2; mt++){
#pragma unroll
            for (int nt = 0; nt < NTILES; nt++){
                const int col = wn * WN + nt * 8 + cc;
                float* p0 = C + (size_t)(r0 + mt * 16) * ldc + col;
                float* p1 = C + (size_t)(r0 + mt * 16 + 8) * ldc + col;
                *reinterpret_cast<float2*>(p0) = make_float2(acc[mt][nt][0], acc[mt][nt][1]);
                *reinterpret_cast<float2*>(p1) = make_float2(acc[mt][nt][2], acc[mt][nt][3]);
            }
        }
    }
}

// ============================ GEMM wrappers ===============================
__global__ __launch_bounds__(256)
void k_proj2_f16(const __half* __restrict__ Ah, const __half* __restrict__ Al,
                 const __half* __restrict__ Bp, __half* __restrict__ C)
{
    size_t ao = (size_t)blockIdx.y * 128 * DM;
    size_t bo = (size_t)blockIdx.x * 128 * DM;
    __half* Cp = C + (size_t)blockIdx.y * 128 * DM + blockIdx.x * 128;
    gemm2_core<128, true>(Ah + ao, Al + ao, DM, Bp + bo, DM, Cp, DM, DM);
}

__global__ __launch_bounds__(256)
void k_projcat2_f16(const __half* __restrict__ Mh, const __half* __restrict__ Ml,
                    const __half* __restrict__ Hh, const __half* __restrict__ Hl,
                    const __half* __restrict__ Bp, __half* __restrict__ C)
{
    const int b = blockIdx.z, m0 = blockIdx.y * 128;
    const __half *Ah, *Al;
    if (m0 < ML){ size_t o = ((size_t)b * ML + m0) * DM; Ah = Mh + o; Al = Ml + o; }
    else        { size_t o = ((size_t)b * QL + (m0 - ML)) * DM; Ah = Hh + o; Al = Hl + o; }
    size_t bo = (size_t)blockIdx.x * 128 * DM;
    __half* Cp = C + ((size_t)b * KL + m0) * DM + blockIdx.x * 128;
    gemm2_core<128, true>(Ah, Al, DM, Bp + bo, DM, Cp, DM, DM);
}

// ============= out projection: A plain x B plain, 1 combo ================
__global__ __launch_bounds__(256)
void k_proj1(const __half* __restrict__ Ap, const __half* __restrict__ Bp,
             float* __restrict__ C)
{
    __shared__ __align__(1024) uint8_t sA[16384];
    __shared__ __align__(1024) uint8_t sB[16384];

    const int tid  = threadIdx.x;
    const int wid  = tid >> 5;
    const int lane = tid & 31;
    const int wm   = wid & 3;
    const int wn   = wid >> 2;

    const int m0 = blockIdx.y * 128, n0 = blockIdx.x * 128;
    const uint32_t a32 = smem_u32(sA), b32 = smem_u32(sB);

    float acc[2][8][4];
#pragma unroll
    for (int mt = 0; mt < 2; mt++)
#pragma unroll
        for (int nt = 0; nt < 8; nt++)
#pragma unroll
            for (int q = 0; q < 4; q++) acc[mt][nt][q] = 0.0f;

    uint4 pa[4], pb[4];
    auto ldg_chunk = [&](int k0){
#pragma unroll
        for (int i = 0; i < 4; i++){
            int s = tid + (i << 8); int row = s >> 3, j = s & 7;
            pa[i] = *reinterpret_cast<const uint4*>(Ap + (size_t)(m0 + row) * DM + k0 + j * 8);
        }
#pragma unroll
        for (int i = 0; i < 4; i++){
            int s = tid + (i << 8); int row = s >> 3, j = s & 7;
            pb[i] = *reinterpret_cast<const uint4*>(Bp + (size_t)(n0 + row) * DM + k0 + j * 8);
        }
    };

    const uint32_t aRowOff0 = (uint32_t)((wm * 32 + (lane & 15)) << 7) + ((lane >> 4) << 4);
    const uint32_t bRowOff  = (uint32_t)((wn * 64 + (lane & 7)) << 7) + (((lane >> 3) & 1) << 4);

    ldg_chunk(0);

    for (int c = 0; c < DM / 64; c++){
#pragma unroll
        for (int i = 0; i < 4; i++){
            int s = tid + (i << 8);
            uint32_t off = SWZ((uint32_t)((s >> 3) << 7) + (uint32_t)((s & 7) << 4));
            *reinterpret_cast<uint4*>(sA + off) = pa[i];
        }
#pragma unroll
        for (int i = 0; i < 4; i++){
            int s = tid + (i << 8);
            uint32_t off = SWZ((uint32_t)((s >> 3) << 7) + (uint32_t)((s & 7) << 4));
            *reinterpret_cast<uint4*>(sB + off) = pb[i];
        }
        __syncthreads();

        if (c + 1 < DM / 64) ldg_chunk((c + 1) << 6);

#pragma unroll
        for (int s16 = 0; s16 < 4; s16++){
            const uint32_t kOff = (uint32_t)(s16 << 5);

            uint32_t av[2][4];
#pragma unroll
            for (int mt = 0; mt < 2; mt++){
                uint32_t base = aRowOff0 + (uint32_t)(mt << 11);
                ldsm_x4(av[mt][0], av[mt][1], av[mt][2], av[mt][3],
                        a32 + SWZ(base + kOff));
            }
#pragma unroll
            for (int nt = 0; nt < 8; nt++){
                uint32_t bb[2];
                ldsm_x2(bb[0], bb[1], b32 + SWZ(bRowOff + (uint32_t)(nt << 10) + kOff));
                mma16816(acc[0][nt], av[0], bb);
                mma16816(acc[1][nt], av[1], bb);
            }
        }
        __syncthreads();
    }

    float* Cp = C + (size_t)m0 * DM + n0;
    const int r0 = wm * 32 + (lane >> 2);
    const int cc = (lane & 3) * 2;
#pragma unroll
    for (int mt = 0; mt < 2; mt++){
#pragma unroll
        for (int nt = 0; nt < 8; nt++){
            const int col = wn * 64 + nt * 8 + cc;
            float* p0 = Cp + (size_t)(r0 + mt * 16) * DM + col;
            float* p1 = Cp + (size_t)(r0 + mt * 16 + 8) * DM + col;
            *reinterpret_cast<float2*>(p0) = make_float2(acc[mt][nt][0], acc[mt][nt][1]);
            *reinterpret_cast<float2*>(p1) = make_float2(acc[mt][nt][2], acc[mt][nt][3]);
        }
    }
}

// ====== merged score kernel: z<32 -> ac (K, batched); z>=32 -> bd (R) =====
// Q split x B plain fp16, K=64, 2-combo, fp32 out.
__global__ __launch_bounds__(256)
void k_score2m(const __half* __restrict__ QWh, const __half* __restrict__ QWl,
               const __half* __restrict__ QRh, const __half* __restrict__ QRl,
               const __half* __restrict__ Kp,  const __half* __restrict__ RHp,
               float* __restrict__ Sout, float* __restrict__ BDout)
{
    __shared__ __align__(1024) uint8_t sA[32768];
    __shared__ __align__(1024) uint8_t sB[16384];

    const int tid  = threadIdx.x;
    const int wid  = tid >> 5;
    const int lane = tid & 31;
    const int wm   = wid & 3;
    const int wn   = wid >> 2;

    const int zr = blockIdx.z;
    const int isAC = (zr < 32);
    const int z = isAC ? zr : (zr - 32);
    const int b = z >> 4, h = z & 15;
    const int i0 = blockIdx.y * 128, j0 = blockIdx.x * 128;
    const int hoff = h * DH;

    const __half* Qh = isAC ? QWh : QRh;
    const __half* Ql = isAC ? QWl : QRl;
    const __half* Bp = isAC ? Kp  : RHp;
    float* Out = isAC ? Sout : BDout;

    const uint32_t a32 = smem_u32(sA), b32 = smem_u32(sB);

    {
        const size_t abase = ((size_t)(b * QL + i0)) * DM + hoff;
#pragma unroll
        for (int i = 0; i < 8; i++){
            int s = tid + (i << 8);
            int pg = s >> 10, rem = s & 1023, row = rem >> 3, j = rem & 7;
            const __half* src = (j < 4)
                ? Qh + abase + (size_t)row * DM + pg * 32 + j * 8
                : Ql + abase + (size_t)row * DM + pg * 32 + (j - 4) * 8;
            uint32_t off = (uint32_t)(pg * 16384) + SWZ((uint32_t)(row << 7) + (uint32_t)(j << 4));
            *reinterpret_cast<uint4*>(sA + off) = *reinterpret_cast<const uint4*>(src);
        }
    }
    {
        const size_t bbase = isAC ? ((size_t)(b * KL + j0)) * DM + hoff
                                  : (size_t)j0 * DM + hoff;
#pragma unroll
        for (int i = 0; i < 4; i++){
            int s = tid + (i << 8);
            int row = s >> 3, j = s & 7;
            const __half* src = Bp + bbase + (size_t)row * DM + j * 8;
            uint32_t off = SWZ((uint32_t)(row << 7) + (uint32_t)(j << 4));
            *reinterpret_cast<uint4*>(sB + off) = *reinterpret_cast<const uint4*>(src);
        }
    }
    __syncthreads();

    float acc[2][8][4];
#pragma unroll
    for (int mt = 0; mt < 2; mt++)
#pragma unroll
        for (int nt = 0; nt < 8; nt++)
#pragma unroll
            for (int q = 0; q < 4; q++) acc[mt][nt][q] = 0.0f;

    const uint32_t aRowOff0 = (uint32_t)((wm * 32 + (lane & 15)) << 7) + ((lane >> 4) << 4);
    const uint32_t bRowOff  = (uint32_t)((wn * 64 + (lane & 7)) << 7) + (((lane >> 3) & 1) << 4);

#pragma unroll
    for (int s16 = 0; s16 < 4; s16++){
        const uint32_t apg = (uint32_t)(s16 >> 1) * 16384u;
        const uint32_t hiOff = (uint32_t)((s16 & 1) << 5);
        const uint32_t bOff  = (uint32_t)(s16 << 5);

        uint32_t ah[2][4], al[2][4];
#pragma unroll
        for (int mt = 0; mt < 2; mt++){
            uint32_t base = aRowOff0 + (uint32_t)(mt << 11);
            ldsm_x4(ah[mt][0], ah[mt][1], ah[mt][2], ah[mt][3],
                    a32 + apg + SWZ(base + hiOff));
            ldsm_x4(al[mt][0], al[mt][1], al[mt][2], al[mt][3],
                    a32 + apg + SWZ(base + hiOff + 64));
        }
#pragma unroll
        for (int nt = 0; nt < 8; nt++){
            uint32_t bb[2];
            ldsm_x2(bb[0], bb[1], b32 + SWZ(bRowOff + (uint32_t)(nt << 10) + bOff));
            mma16816(acc[0][nt], ah[0], bb);
            mma16816(acc[1][nt], ah[1], bb);
            mma16816(acc[0][nt], al[0], bb);
            mma16816(acc[1][nt], al[1], bb);
        }
    }

    float* Cp = Out + ((size_t)z * QL + i0) * KL + j0;
    const int r0 = wm * 32 + (lane >> 2);
    const int cc = (lane & 3) * 2;
#pragma unroll
    for (int mt = 0; mt < 2; mt++){
#pragma unroll
        for (int nt = 0; nt < 8; nt++){
            const int col = wn * 64 + nt * 8 + cc;
            float* p0 = Cp + (size_t)(r0 + mt * 16) * KL + col;
            float* p1 = Cp + (size_t)(r0 + mt * 16 + 8) * KL + col;
            *reinterpret_cast<float2*>(p0) = make_float2(acc[mt][nt][0], acc[mt][nt][1]);
            *reinterpret_cast<float2*>(p1) = make_float2(acc[mt][nt][2], acc[mt][nt][3]);
        }
    }
}

// ===== av kernel: P plain fp16 x V plain fp16 (trans-B), 1 combo =========
__global__ __launch_bounds__(256)
void k_av3(const __half* __restrict__ P, const __half* __restrict__ Vp,
           __half* __restrict__ AV)
{
    __shared__ __align__(1024) uint8_t sA[16384];
    __shared__ __align__(1024) uint8_t sB[8192];

    const int tid  = threadIdx.x;
    const int wid  = tid >> 5;
    const int lane = tid & 31;
    const int wm   = wid & 3;
    const int wn   = wid >> 2;

    const int z = blockIdx.z, b = z >> 4, h = z & 15;
    const int i0 = blockIdx.y * 128;
    const size_t prow = (size_t)z * QL + i0;
    const size_t vbase = (size_t)b * KL * DM + h * DH;

    const uint32_t a32 = smem_u32(sA), b32 = smem_u32(sB);

    float acc[2][4][4];
#pragma unroll
    for (int mt = 0; mt < 2; mt++)
#pragma unroll
        for (int nt = 0; nt < 4; nt++)
#pragma unroll
            for (int q = 0; q < 4; q++) acc[mt][nt][q] = 0.0f;

    uint4 pa[4], pb[2];
    auto ldg_chunk = [&](int k0){
#pragma unroll
        for (int i = 0; i < 4; i++){
            int s = tid + (i << 8); int row = s >> 3, j = s & 7;
            pa[i] = *reinterpret_cast<const uint4*>(P + (prow + row) * KL + k0 + j * 8);
        }
#pragma unroll
        for (int i = 0; i < 2; i++){
            int s = tid + (i << 8); int row = s >> 3, j = s & 7;
            pb[i] = *reinterpret_cast<const uint4*>(Vp + vbase + (size_t)(k0 + row) * DM + j * 8);
        }
    };

    const uint32_t aRowOff0 = (uint32_t)((wm * 32 + (lane & 15)) << 7) + ((lane >> 4) << 4);
    const uint32_t n0byte   = (uint32_t)((wn * 32) << 1);

    ldg_chunk(0);

    for (int c = 0; c < KL / 64; c++){
#pragma unroll
        for (int i = 0; i < 4; i++){
            int s = tid + (i << 8);
            uint32_t off = SWZ((uint32_t)((s >> 3) << 7) + (uint32_t)((s & 7) << 4));
            *reinterpret_cast<uint4*>(sA + off) = pa[i];
        }
#pragma unroll
        for (int i = 0; i < 2; i++){
            int s = tid + (i << 8);
            uint32_t off = SWZ((uint32_t)((s >> 3) << 7) + (uint32_t)((s & 7) << 4));
            *reinterpret_cast<uint4*>(sB + off) = pb[i];
        }
        __syncthreads();

        if (c + 1 < KL / 64) ldg_chunk((c + 1) << 6);

#pragma unroll
        for (int s16 = 0; s16 < 4; s16++){
            const uint32_t aOff = (uint32_t)(s16 << 5);

            uint32_t av[2][4];
#pragma unroll
            for (int mt = 0; mt < 2; mt++){
                uint32_t base = aRowOff0 + (uint32_t)(mt << 11);
                ldsm_x4(av[mt][0], av[mt][1], av[mt][2], av[mt][3],
                        a32 + SWZ(base + aOff));
            }
            const uint32_t brow = (uint32_t)(((s16 << 4) + (lane & 15)) << 7);
#pragma unroll
            for (int nt = 0; nt < 4; nt++){
                uint32_t bb[2];
                ldsm_x2t(bb[0], bb[1], b32 + SWZ(brow + n0byte + (uint32_t)(nt << 4)));
                mma16816(acc[0][nt], av[0], bb);
                mma16816(acc[1][nt], av[1], bb);
            }
        }
        __syncthreads();
    }

    __half* Cp = AV + ((size_t)(b * QL + i0)) * DM + h * DH;
    const int r0 = wm * 32 + (lane >> 2);
    const int cc = (lane & 3) * 2;
#pragma unroll
    for (int mt = 0; mt < 2; mt++){
#pragma unroll
        for (int nt = 0; nt < 4; nt++){
            const int col = wn * 32 + nt * 8 + cc;
            __half2 v0 = __floats2half2_rn(acc[mt][nt][0], acc[mt][nt][1]);
            __half2 v1 = __floats2half2_rn(acc[mt][nt][2], acc[mt][nt][3]);
            *reinterpret_cast<__half2*>(Cp + (size_t)(r0 + mt * 16) * DM + col)     = v0;
            *reinterpret_cast<__half2*>(Cp + (size_t)(r0 + mt * 16 + 8) * DM + col) = v1;
        }
    }
}

// ============================ conversions =================================
__device__ __forceinline__ void split1(float x, __half& h, __half& l){
    h = __float2half(x);
    l = __float2half(x - __half2float(h));
}

// Merged input splits: seg 0 = h, 1 = mem, 2 = r (each SZ_2M elements).
__global__ __launch_bounds__(256)
void k_split3(const float* __restrict__ x0, const float* __restrict__ x1,
              const float* __restrict__ x2,
              __half* __restrict__ h0, __half* __restrict__ l0,
              __half* __restrict__ h1, __half* __restrict__ l1,
              __half* __restrict__ h2, __half* __restrict__ l2)
{
    const int seg = blockIdx.y;
    const float* x = (seg == 0) ? x0 : (seg == 1) ? x1 : x2;
    __half* h = (seg == 0) ? h0 : (seg == 1) ? h1 : h2;
    __half* l = (seg == 0) ? l0 : (seg == 1) ? l1 : l2;

    size_t i = ((size_t)blockIdx.x * 256 + threadIdx.x) * 4;
    float4 v = *reinterpret_cast<const float4*>(x + i);
    __half a0, a1, a2, a3, b0, b1, b2, b3;
    split1(v.x, a0, b0); split1(v.y, a1, b1);
    split1(v.z, a2, b2); split1(v.w, a3, b3);
    *reinterpret_cast<__half2*>(h + i)     = __halves2half2(a0, a1);
    *reinterpret_cast<__half2*>(h + i + 2) = __halves2half2(a2, a3);
    *reinterpret_cast<__half2*>(l + i)     = __halves2half2(b0, b1);
    *reinterpret_cast<__half2*>(l + i + 2) = __halves2half2(b2, b3);
}

// Merged weight transpose-splits: z = weight index 0..4.
// out[z][c][r] = split(W[z][r][c]); 1024x1024 each.
__global__ __launch_bounds__(256)
void k_tsplit5(const float* __restrict__ w0, const float* __restrict__ w1,
               const float* __restrict__ w2, const float* __restrict__ w3,
               const float* __restrict__ w4, __half* __restrict__ dstbase)
{
    __shared__ float t[32][33];
    const int z = blockIdx.z;
    const float* xb = (z == 0) ? w0 : (z == 1) ? w1 : (z == 2) ? w2 : (z == 3) ? w3 : w4;
    __half* ph = dstbase + (size_t)z * 2 * SZ_1M;
    __half* pl = ph + SZ_1M;
    const int c0 = blockIdx.x * 32, r0 = blockIdx.y * 32;
    const int tx = threadIdx.x, ty = threadIdx.y;
    for (int i = ty; i < 32; i += 8)
        t[i][tx] = xb[(size_t)(r0 + i) * 1024 + c0 + tx];
    __syncthreads();
    for (int i = ty; i < 32; i += 8){
        __half h, l; split1(t[tx][i], h, l);
        ph[(size_t)(c0 + i) * 1024 + r0 + tx] = h;
        pl[(size_t)(c0 + i) * 1024 + r0 + tx] = l;
    }
}

// ============================ softmax (fp32 in) ===========================
__global__ __launch_bounds__(256)
void k_softmax(const float* __restrict__ S, const float* __restrict__ BD,
               __half* __restrict__ Pp)
{
    const int row = blockIdx.x;
    const int i   = row & (QL - 1);
    const float* srow = S + (size_t)row * KL;
    const float* x0 = BD + (size_t)row * KL;
    const float* x1 = x0 + KL;

    const int tid = threadIdx.x, lane = tid & 31, warp = tid >> 5;
    __shared__ float red[8];

    float sc[8];
    float mx = -1e30f;
#pragma unroll
    for (int c = 0; c < 8; c++){
        const int j = c * 256 + tid;
        const int d = j - i;
        float bdv;
        if (d <= QL)           bdv = x0[j - i + (QL - 1)];
        else if (d == QL + 1)  bdv = 0.0f;
        else                   bdv = x1[j - i - (QL + 2)];
        const float v = (srow[j] + bdv) * 0.125f;
        sc[c] = v;
        mx = fmaxf(mx, v);
    }
#pragma unroll
    for (int o = 16; o > 0; o >>= 1) mx = fmaxf(mx, __shfl_xor_sync(0xffffffffu, mx, o));
    if (lane == 0) red[warp] = mx;
    __syncthreads();
    float rowmax = red[0];
#pragma unroll
    for (int w = 1; w < 8; w++) rowmax = fmaxf(rowmax, red[w]);
    __syncthreads();

    float sum = 0.0f;
#pragma unroll
    for (int c = 0; c < 8; c++){ sc[c] = __expf(sc[c] - rowmax); sum += sc[c]; }
#pragma unroll
    for (int o = 16; o > 0; o >>= 1) sum += __shfl_xor_sync(0xffffffffu, sum, o);
    if (lane == 0) red[warp] = sum;
    __syncthreads();
    float rowsum = 0.0f;
#pragma unroll
    for (int w = 0; w < 8; w++) rowsum += red[w];
    const float inv = 1.0f / rowsum;

    __half* ph = Pp + (size_t)row * KL;
#pragma unroll
    for (int c = 0; c < 8; c++){
        const int j = c * 256 + tid;
        ph[j] = __float2half(sc[c] * inv);
    }
}

// ============================ launch ======================================
extern "C" void kernel_launch(void* const* d_in, const int* in_sizes, int n_in,
                              void* d_out, int out_size)
{
    const float* h_in  = (const float*)d_in[0];
    const float* mem_p = (const float*)d_in[1];
    const float* r_p   = (const float*)d_in[2];
    const float* W[5]  = { (const float*)d_in[3], (const float*)d_in[4],
                           (const float*)d_in[5], (const float*)d_in[6],
                           (const float*)d_in[7] };   // Wq, Wk, Wv, Wr, Wo
    const float* rwb   = (const float*)d_in[8];
    const float* rrb   = (const float*)d_in[9];
    float* out = (float*)d_out;

    __half* hf; float* fp;
    cudaGetSymbolAddress((void**)&hf, g_hf);
    cudaGetSymbolAddress((void**)&fp, g_f);

    // 1) split inputs (one launch)
    k_split3<<<dim3(2048, 3), 256>>>(h_in, mem_p, r_p,
                                     hf + oHSPh, hf + oHSPl,
                                     hf + oMSPh, hf + oMSPl,
                                     hf + oRSPh, hf + oRSPl);

    // 2) transpose+split all 5 weights (one launch)
    k_tsplit5<<<dim3(32, 32, 5), dim3(32, 8)>>>(W[0], W[1], W[2], W[3], W[4], hf + oWT);
    const __half *wq = hf + oWT,            *wk = hf + oWT + 2 * SZ_1M,
                 *wv = hf + oWT + 4 * SZ_1M, *wr = hf + oWT + 6 * SZ_1M,
                 *wo = hf + oWT + 8 * SZ_1M;

    // 3) projections
    k_projq<<<dim3(8, 16), 256>>>(hf + oHSPh, hf + oHSPl, wq, wq + SZ_1M,
                                  rwb, rrb,
                                  hf + oQWh, hf + oQWl, hf + oQRh, hf + oQRl); // Q + bias-split fused
    k_projcat2_f16<<<dim3(8, 16, 2), 256>>>(hf + oMSPh, hf + oMSPl,
                                            hf + oHSPh, hf + oHSPl, wk, hf + oKp); // K
    k_projcat2_f16<<<dim3(8, 16, 2), 256>>>(hf + oMSPh, hf + oMSPl,
                                            hf + oHSPh, hf + oHSPl, wv, hf + oVp); // V
    k_proj2_f16<<<dim3(8, 16), 256>>>(hf + oRSPh, hf + oRSPl, wr, hf + oRHp);      // R

    // 4) scores: ac + bd merged (2-combo fp16, fp32 out)
    k_score2m<<<dim3(16, 8, 64), 256>>>(hf + oQWh, hf + oQWl, hf + oQRh, hf + oQRl,
                                        hf + oKp, hf + oRHp, fp + fS, fp + fBD);

    // 5) fused rel_shift + softmax -> plain fp16 probs
    k_softmax<<<B_SZ * NH * QL, 256>>>(fp + fS, fp + fBD, hf + oPp);

    // 6) attn_vec = prob @ v (1-combo) -> plain fp16
    k_av3<<<dim3(1, 8, 32), 256>>>(hf + oPp, hf + oVp, hf + oAVp);

    // 7) out = attn_vec @ Wo (1-combo, fp32 out)
    k_proj1<<<dim3(8, 16), 256>>>(hf + oAVp, wo, out);
}